// round 1
// baseline (speedup 1.0000x reference)
#include <cuda_runtime.h>
#include <cstddef>
#include <math.h>

// Problem constants
#define BSZ 64
#define LEN 512
#define DIM 1024
#define NH  16
#define DKH 64

// Derived
#define M_KQ (64 + BSZ*LEN)   // 32832 rows: [q (64); k (32768)]
#define M_KV (BSZ*LEN)        // 32768
#define OUT_MAIN_ELEMS ((size_t)BSZ*LEN*DIM)   // 33,554,432

// -------------------- scratch (device globals, no allocs) --------------------
__device__ float g_kpq[(size_t)M_KQ * DIM];          // [q;k] projections
__device__ float g_scores[(size_t)BSZ * NH * LEN];   // scores[b][h][l]
__device__ float g_back[(size_t)BSZ * NH * LEN];     // sigmoid gate
__device__ float g_concat[(size_t)M_KV * DIM];       // gated vp (concat)

// ============================================================================
// Generic tiled SGEMM:  C[m][n] = (sum_k A[m][k] * W[n][k]) + bias[n]
// BM=BN=128, BK=16, 256 threads, 8x8 microtile, reg->smem pipelined.
// GATHER: A rows 0..63 come from Aq, rows 64.. from A (k tensor).
// GATE:   multiply output by g_back[b][h][l] (b=m>>9, l=m&511, h=n>>6).
// ============================================================================
template<bool GATHER, bool GATE>
__global__ __launch_bounds__(256, 2)
void sgemm_kernel(const float* __restrict__ A,
                  const float* __restrict__ Aq,
                  const float* __restrict__ W,     // [N][K] row-major
                  const float* __restrict__ bias,  // [N]
                  const float* __restrict__ gate,  // [BSZ*NH*LEN] or null
                  float* __restrict__ C,
                  int M, int N, int K)
{
    __shared__ float As[16][132];
    __shared__ float Bs[16][132];

    const int tid = threadIdx.x;
    const int m0  = blockIdx.x * 128;
    const int n0  = blockIdx.y * 128;

    // ---- gmem load assignment: 512 float4 per operand tile, 2 per thread ----
    const int ar0 = tid >> 2;            // 0..63
    const int ac0 = (tid & 3) * 4;       // {0,4,8,12}
    const int grow0 = m0 + ar0;
    const int grow1 = m0 + ar0 + 64;
    const bool v0 = grow0 < M;
    const bool v1 = grow1 < M;

    const float* p0;
    const float* p1;
    if (GATHER) {
        p0 = (grow0 < 64) ? (Aq + (size_t)grow0 * K) : (A + (size_t)(grow0 - 64) * K);
        p1 = (grow1 < 64) ? (Aq + (size_t)grow1 * K) : (A + (size_t)(grow1 - 64) * K);
        if (!v0) p0 = Aq;   // safe dummy, value zeroed
        if (!v1) p1 = Aq;
    } else {
        p0 = A + (size_t)(v0 ? grow0 : 0) * K;
        p1 = A + (size_t)(v1 ? grow1 : 0) * K;
    }
    const float* q0 = W + (size_t)(n0 + ar0) * K;
    const float* q1 = W + (size_t)(n0 + ar0 + 64) * K;

    const float4 z4 = make_float4(0.f, 0.f, 0.f, 0.f);

    float4 ta0, ta1, tb0, tb1;
    // prologue fetch (k0 = 0)
    ta0 = v0 ? *(const float4*)(p0 + ac0) : z4;
    ta1 = v1 ? *(const float4*)(p1 + ac0) : z4;
    tb0 = *(const float4*)(q0 + ac0);
    tb1 = *(const float4*)(q1 + ac0);

    const int tx = tid & 15;
    const int ty = tid >> 4;

    float acc[8][8];
    #pragma unroll
    for (int i = 0; i < 8; i++)
        #pragma unroll
        for (int j = 0; j < 8; j++) acc[i][j] = 0.f;

    for (int k0 = 0; k0 < K; k0 += 16) {
        __syncthreads();
        // store fetched tile (transposed) to smem
        As[ac0+0][ar0]    = ta0.x; As[ac0+1][ar0]    = ta0.y;
        As[ac0+2][ar0]    = ta0.z; As[ac0+3][ar0]    = ta0.w;
        As[ac0+0][ar0+64] = ta1.x; As[ac0+1][ar0+64] = ta1.y;
        As[ac0+2][ar0+64] = ta1.z; As[ac0+3][ar0+64] = ta1.w;
        Bs[ac0+0][ar0]    = tb0.x; Bs[ac0+1][ar0]    = tb0.y;
        Bs[ac0+2][ar0]    = tb0.z; Bs[ac0+3][ar0]    = tb0.w;
        Bs[ac0+0][ar0+64] = tb1.x; Bs[ac0+1][ar0+64] = tb1.y;
        Bs[ac0+2][ar0+64] = tb1.z; Bs[ac0+3][ar0+64] = tb1.w;
        __syncthreads();

        if (k0 + 16 < K) {
            const int kn = k0 + 16;
            ta0 = v0 ? *(const float4*)(p0 + kn + ac0) : z4;
            ta1 = v1 ? *(const float4*)(p1 + kn + ac0) : z4;
            tb0 = *(const float4*)(q0 + kn + ac0);
            tb1 = *(const float4*)(q1 + kn + ac0);
        }

        #pragma unroll
        for (int kk = 0; kk < 16; kk++) {
            float4 a0 = *(const float4*)&As[kk][ty*4];
            float4 a1 = *(const float4*)&As[kk][64 + ty*4];
            float4 b0 = *(const float4*)&Bs[kk][tx*4];
            float4 b1 = *(const float4*)&Bs[kk][64 + tx*4];
            float ra[8] = {a0.x,a0.y,a0.z,a0.w,a1.x,a1.y,a1.z,a1.w};
            float rb[8] = {b0.x,b0.y,b0.z,b0.w,b1.x,b1.y,b1.z,b1.w};
            #pragma unroll
            for (int i = 0; i < 8; i++)
                #pragma unroll
                for (int j = 0; j < 8; j++)
                    acc[i][j] = fmaf(ra[i], rb[j], acc[i][j]);
        }
    }

    // ---- epilogue ----
    const int c0 = n0 + tx*4;
    const int c1 = n0 + 64 + tx*4;
    const float4 bias0 = *(const float4*)&bias[c0];
    const float4 bias1 = *(const float4*)&bias[c1];
    const int h0 = c0 >> 6;  // head for col group 0 (4 cols never cross a 64-boundary)
    const int h1 = c1 >> 6;

    #pragma unroll
    for (int i = 0; i < 8; i++) {
        const int rr = m0 + ((i < 4) ? (ty*4 + i) : (64 + ty*4 + i - 4));
        if (rr >= M) continue;
        float g0 = 1.f, g1 = 1.f;
        if (GATE) {
            const int bb = rr >> 9;
            const int ll = rr & 511;
            g0 = gate[((size_t)bb * NH + h0) * LEN + ll];
            g1 = gate[((size_t)bb * NH + h1) * LEN + ll];
        }
        float4 o0, o1;
        o0.x = (acc[i][0] + bias0.x) * g0;
        o0.y = (acc[i][1] + bias0.y) * g0;
        o0.z = (acc[i][2] + bias0.z) * g0;
        o0.w = (acc[i][3] + bias0.w) * g0;
        o1.x = (acc[i][4] + bias1.x) * g1;
        o1.y = (acc[i][5] + bias1.y) * g1;
        o1.z = (acc[i][6] + bias1.z) * g1;
        o1.w = (acc[i][7] + bias1.w) * g1;
        *(float4*)&C[(size_t)rr * N + c0] = o0;
        *(float4*)&C[(size_t)rr * N + c1] = o1;
    }
}

// ============================================================================
// scores[b][h][j] = dot64(qp[b,h,:], kp[b,j,h,:]) / 8
// qp = g_kpq row b; kp row = g_kpq[64 + b*512 + j].
// grid (64, 4), 512 threads (warp = head, lane covers 4 j's).
// ============================================================================
__global__ __launch_bounds__(512)
void scores_kernel(float* __restrict__ scores)
{
    const int b  = blockIdx.x;
    const int jq = blockIdx.y;
    __shared__ float qp_s[DIM];
    const int t = threadIdx.x;
    for (int i = t; i < DIM; i += 512) qp_s[i] = g_kpq[(size_t)b * DIM + i];
    __syncthreads();

    const int h = t >> 5;
    const int lane = t & 31;
    const float4* qv = (const float4*)&qp_s[h * DKH];

    #pragma unroll
    for (int jj = 0; jj < 4; jj++) {
        const int j = jq * 128 + jj * 32 + lane;
        const float4* kv =
            (const float4*)(g_kpq + (size_t)(64 + b * LEN + j) * DIM + h * DKH);
        float s = 0.f;
        #pragma unroll
        for (int d = 0; d < 16; d++) {
            float4 a = qv[d];
            float4 c = kv[d];
            s = fmaf(a.x, c.x, s); s = fmaf(a.y, c.y, s);
            s = fmaf(a.z, c.z, s); s = fmaf(a.w, c.w, s);
        }
        scores[((size_t)b * NH + h) * LEN + j] = s * 0.125f;
    }
}

// ============================================================================
// qe_score[b][h][i] = sum_j qe[b][i][j] * scores[b][h][j]
// back = sigmoid(lambda_h * cw[b][i] + (1-lambda_h) * qe_score)
// fcw[b][i] = qe_score[b][0][i]   (pre-sigmoid, head 0)
// grid (64, 8): (b, 64-row i-block); 256 threads: thread = (i_local, 4 heads).
// ============================================================================
__global__ __launch_bounds__(256)
void qe_kernel(const float* __restrict__ qe,
               const float* __restrict__ cw,
               const float* __restrict__ lambdas,
               const float* __restrict__ scores,
               float* __restrict__ back,
               float* __restrict__ fcw)
{
    __shared__ float sc_s[NH][513];
    __shared__ float qe_t[64][33];

    const int b  = blockIdx.x;
    const int i0 = blockIdx.y * 64;
    const int t  = threadIdx.x;

    for (int i = t; i < NH * LEN; i += 256)
        sc_s[i >> 9][i & 511] = scores[(size_t)b * NH * LEN + i];

    const int il = t >> 2;
    const int hg = t & 3;
    float acc[4] = {0.f, 0.f, 0.f, 0.f};

    for (int jc = 0; jc < 16; jc++) {
        __syncthreads();   // also covers initial sc_s fill
        #pragma unroll
        for (int p = 0; p < 8; p++) {
            const int f = t + p * 256;
            const int r = f >> 5, c = f & 31;
            qe_t[r][c] = qe[((size_t)b * LEN + i0 + r) * LEN + jc * 32 + c];
        }
        __syncthreads();
        #pragma unroll
        for (int jj = 0; jj < 32; jj++) {
            const float qv = qe_t[il][jj];
            const int j = jc * 32 + jj;
            acc[0] = fmaf(qv, sc_s[hg     ][j], acc[0]);
            acc[1] = fmaf(qv, sc_s[hg + 4 ][j], acc[1]);
            acc[2] = fmaf(qv, sc_s[hg + 8 ][j], acc[2]);
            acc[3] = fmaf(qv, sc_s[hg + 12][j], acc[3]);
        }
    }

    const float c_w = cw[(size_t)b * LEN + i0 + il];
    #pragma unroll
    for (int c = 0; c < 4; c++) {
        const int h = hg + 4 * c;
        const float lam = lambdas[h];
        const float x = acc[c];
        const float z = lam * c_w + (1.f - lam) * x;
        const float bk = 1.f / (1.f + expf(-z));
        back[((size_t)b * NH + h) * LEN + i0 + il] = bk;
        if (h == 0) fcw[(size_t)b * LEN + i0 + il] = x;
    }
}

// ============================================================================
// launch
// ============================================================================
extern "C" void kernel_launch(void* const* d_in, const int* in_sizes, int n_in,
                              void* d_out, int out_size)
{
    const float* q   = (const float*)d_in[0];   // (64,1,2048)
    const float* k   = (const float*)d_in[1];   // (64,512,2048)
    const float* v   = (const float*)d_in[2];   // (64,512,3072)
    const float* cw  = (const float*)d_in[3];   // (64,512)
    const float* qe  = (const float*)d_in[4];   // (64,512,512)
    const float* Wq  = (const float*)d_in[5];   // (1024,2048)
    const float* bq  = (const float*)d_in[6];   // (1024,)
    const float* Wv  = (const float*)d_in[7];   // (1024,3072)
    const float* bv  = (const float*)d_in[8];   // (1024,)
    const float* Wo  = (const float*)d_in[9];   // (1024,1024)
    const float* bo  = (const float*)d_in[10];  // (1024,)
    const float* lam = (const float*)d_in[11];  // (16,)

    float* out_main = (float*)d_out;                    // (64,512,1024)
    float* out_fcw  = (float*)d_out + OUT_MAIN_ELEMS;   // (64,512)

    float *kpq, *scores, *back, *concat;
    cudaGetSymbolAddress((void**)&kpq,    g_kpq);
    cudaGetSymbolAddress((void**)&scores, g_scores);
    cudaGetSymbolAddress((void**)&back,   g_back);
    cudaGetSymbolAddress((void**)&concat, g_concat);

    // 1. fused [q; k] @ Wq^T + bq  ->  g_kpq  (M = 32832, K = 2048)
    sgemm_kernel<true, false><<<dim3(257, 8), 256>>>(
        k, q, Wq, bq, nullptr, kpq, M_KQ, DIM, 2 * DIM);

    // 2. scores
    scores_kernel<<<dim3(BSZ, 4), 512>>>(scores);

    // 3. qe_score -> back gate + fcw output
    qe_kernel<<<dim3(BSZ, 8), 256>>>(qe, cw, lam, scores, back, out_fcw);

    // 4. v @ Wv^T + bv, gated  ->  g_concat  (M = 32768, K = 3072)
    sgemm_kernel<false, true><<<dim3(256, 8), 256>>>(
        v, nullptr, Wv, bv, back, concat, M_KV, DIM, 3 * DIM);

    // 5. concat @ Wo^T + bo -> main output  (M = 32768, K = 1024)
    sgemm_kernel<false, false><<<dim3(256, 8), 256>>>(
        concat, nullptr, Wo, bo, nullptr, out_main, M_KV, DIM, DIM);
}

// round 3
// speedup vs baseline: 2.5386x; 2.5386x over previous
#include <cuda_runtime.h>
#include <cuda_bf16.h>
#include <cstdint>
#include <cstddef>
#include <math.h>

// Problem constants
#define BSZ 64
#define LEN 512
#define DIM 1024
#define NH  16
#define DKH 64

#define M_KQ 32832           // 64 q rows + 64*512 k rows
#define M_KQ_PAD 32896       // 257 * 128
#define M_KV 32768
#define OUT_MAIN_ELEMS ((size_t)BSZ*LEN*DIM)

// ---------------------------------------------------------------------------
// scratch (__device__ globals; zero-initialized at module load)
// ---------------------------------------------------------------------------
__device__ __nv_bfloat16 g_qk_hi[(size_t)M_KQ_PAD * 2048];
__device__ __nv_bfloat16 g_qk_lo[(size_t)M_KQ_PAD * 2048];
__device__ __nv_bfloat16 g_v_hi[(size_t)M_KV * 3072];
__device__ __nv_bfloat16 g_v_lo[(size_t)M_KV * 3072];
__device__ __nv_bfloat16 g_wq_hi[1024 * 2048];
__device__ __nv_bfloat16 g_wq_lo[1024 * 2048];
__device__ __nv_bfloat16 g_wv_hi[1024 * 3072];
__device__ __nv_bfloat16 g_wv_lo[1024 * 3072];
__device__ __nv_bfloat16 g_wo_hi[1024 * 1024];
__device__ __nv_bfloat16 g_wo_lo[1024 * 1024];
__device__ __nv_bfloat16 g_c_hi[(size_t)M_KV * DIM];
__device__ __nv_bfloat16 g_c_lo[(size_t)M_KV * DIM];
__device__ float g_kpq[(size_t)M_KQ * DIM];
__device__ float g_scores[(size_t)BSZ * NH * LEN];
__device__ float g_back[(size_t)BSZ * NH * LEN];

// ---------------------------------------------------------------------------
// PTX helpers (base sm_103 target — no arch-'a' features)
// ---------------------------------------------------------------------------
__device__ __forceinline__ uint32_t smem_u32(const void* p) {
    uint32_t a;
    asm("{ .reg .u64 t; cvta.to.shared.u64 t, %1; cvt.u32.u64 %0, t; }" : "=r"(a) : "l"(p));
    return a;
}
__device__ __forceinline__ void cpa16(uint32_t s, const void* g) {
    asm volatile("cp.async.cg.shared.global [%0], [%1], 16;" :: "r"(s), "l"(g));
}
__device__ __forceinline__ void cp_commit() {
    asm volatile("cp.async.commit_group;");
}
__device__ __forceinline__ void cp_wait1() {
    asm volatile("cp.async.wait_group 1;");
}
__device__ __forceinline__ void cp_wait0() {
    asm volatile("cp.async.wait_group 0;");
}
__device__ __forceinline__ void ldsm4(uint32_t* r, uint32_t a) {
    asm volatile("ldmatrix.sync.aligned.m8n8.x4.shared.b16 {%0,%1,%2,%3}, [%4];"
                 : "=r"(r[0]), "=r"(r[1]), "=r"(r[2]), "=r"(r[3]) : "r"(a));
}
__device__ __forceinline__ void mma_bf16(float* d, const uint32_t* a, uint32_t b0, uint32_t b1) {
    asm volatile(
        "mma.sync.aligned.m16n8k16.row.col.f32.bf16.bf16.f32 "
        "{%0,%1,%2,%3}, {%4,%5,%6,%7}, {%8,%9}, {%0,%1,%2,%3};"
        : "+f"(d[0]), "+f"(d[1]), "+f"(d[2]), "+f"(d[3])
        : "r"(a[0]), "r"(a[1]), "r"(a[2]), "r"(a[3]), "r"(b0), "r"(b1));
}

// ---------------------------------------------------------------------------
// fp32 -> bf16 hi/lo split conversion
// ---------------------------------------------------------------------------
struct bf4 { __nv_bfloat16 a, b, c, d; };

__global__ void split_kernel(const float4* __restrict__ src,
                             __nv_bfloat16* __restrict__ hi,
                             __nv_bfloat16* __restrict__ lo, size_t n4) {
    size_t i = (size_t)blockIdx.x * blockDim.x + threadIdx.x;
    if (i >= n4) return;
    float4 v = src[i];
    __nv_bfloat16 h0 = __float2bfloat16(v.x);
    __nv_bfloat16 h1 = __float2bfloat16(v.y);
    __nv_bfloat16 h2 = __float2bfloat16(v.z);
    __nv_bfloat16 h3 = __float2bfloat16(v.w);
    bf4 H = {h0, h1, h2, h3};
    bf4 L = {__float2bfloat16(v.x - __bfloat162float(h0)),
             __float2bfloat16(v.y - __bfloat162float(h1)),
             __float2bfloat16(v.z - __bfloat162float(h2)),
             __float2bfloat16(v.w - __bfloat162float(h3))};
    *(bf4*)(hi + i * 4) = H;
    *(bf4*)(lo + i * 4) = L;
}

// ---------------------------------------------------------------------------
// mma.sync split-bf16 GEMM:  C[m][n] = sum_k A[m][k]*B[n][k] + bias[n]
// CTA 128x128, BK=32, 256 thr (8 warps, warp tile 32x64), cp.async 2-stage.
// Smem per stage: 4 comps (Ah,Al,Bh,Bl), 128 rows x 80B = 10240B each.
// OM: 0 = fp32 out, 1 = bf16 hi/lo split out.   G: gate multiply.
// ---------------------------------------------------------------------------
#define STAGE_B  40960
#define COMP_B   10240
#define ROW_B    80

template<int OM, bool G>
__global__ __launch_bounds__(256, 2)
void gemm_mma(const __nv_bfloat16* __restrict__ Ahi, const __nv_bfloat16* __restrict__ Alo,
              const __nv_bfloat16* __restrict__ Bhi, const __nv_bfloat16* __restrict__ Blo,
              const float* __restrict__ bias, const float* __restrict__ gate,
              float* __restrict__ Cf,
              __nv_bfloat16* __restrict__ Chi, __nv_bfloat16* __restrict__ Clo,
              int M, int N, int K)
{
    extern __shared__ __align__(16) char dsm[];
    const int tid  = threadIdx.x;
    const int wid  = tid >> 5;
    const int lane = tid & 31;
    const int wm = wid & 3;       // warp m index (32 rows each)
    const int wn = wid >> 2;      // warp n index (64 cols each)
    const int n0 = blockIdx.x * 128;
    const int m0 = blockIdx.y * 128;
    const uint32_t sbase = smem_u32(dsm);

    const __nv_bfloat16* aH = Ahi + (size_t)m0 * K;
    const __nv_bfloat16* aL = Alo + (size_t)m0 * K;
    const __nv_bfloat16* bH = Bhi + (size_t)n0 * K;
    const __nv_bfloat16* bL = Blo + (size_t)n0 * K;

    // per-thread cp.async slots: idx = j*256+tid -> row=idx>>2, seg=idx&3
    const int r_0 = tid >> 2,       r_1 = (256 + tid) >> 2;
    const int s_0 = (tid & 3) * 8,  s_1 = ((256 + tid) & 3) * 8;   // k-offset (halves)

    float acc[2][8][4];
    #pragma unroll
    for (int a = 0; a < 2; a++)
        #pragma unroll
        for (int b = 0; b < 8; b++)
            #pragma unroll
            for (int c = 0; c < 4; c++) acc[a][b][c] = 0.f;

    const int NC = K >> 5;   // BK=32 chunks

    // ---- issue helper (macro-free, inline) ----
    auto issue = [&](int c) {
        const int kc = c << 5;
        const uint32_t sb = sbase + (uint32_t)(c & 1) * STAGE_B;
        // Ah
        cpa16(sb + 0*COMP_B + r_0*ROW_B + s_0*2, aH + (size_t)r_0 * K + kc + s_0);
        cpa16(sb + 0*COMP_B + r_1*ROW_B + s_1*2, aH + (size_t)r_1 * K + kc + s_1);
        // Al
        cpa16(sb + 1*COMP_B + r_0*ROW_B + s_0*2, aL + (size_t)r_0 * K + kc + s_0);
        cpa16(sb + 1*COMP_B + r_1*ROW_B + s_1*2, aL + (size_t)r_1 * K + kc + s_1);
        // Bh
        cpa16(sb + 2*COMP_B + r_0*ROW_B + s_0*2, bH + (size_t)r_0 * K + kc + s_0);
        cpa16(sb + 2*COMP_B + r_1*ROW_B + s_1*2, bH + (size_t)r_1 * K + kc + s_1);
        // Bl
        cpa16(sb + 3*COMP_B + r_0*ROW_B + s_0*2, bL + (size_t)r_0 * K + kc + s_0);
        cpa16(sb + 3*COMP_B + r_1*ROW_B + s_1*2, bL + (size_t)r_1 * K + kc + s_1);
        cp_commit();
    };

    issue(0);

    const int arow = wm * 32 + (lane & 15);
    const int acol = (lane >> 4) * 16;                         // bytes within 32B k-half
    const int brow = wn * 64 + ((lane >> 4) << 3) + (lane & 7);
    const int bcol = ((lane >> 3) & 1) * 16;                   // bytes

    for (int c = 0; c < NC; c++) {
        if (c + 1 < NC) { issue(c + 1); cp_wait1(); }
        else            { cp_wait0(); }
        __syncthreads();

        const uint32_t sb = sbase + (uint32_t)(c & 1) * STAGE_B;

        #pragma unroll
        for (int ks = 0; ks < 2; ks++) {
            const uint32_t kb = ks * 32;   // byte offset of k16 step
            uint32_t Ah[2][4], Al[2][4], B[4][4];
            #pragma unroll
            for (int mt = 0; mt < 2; mt++) {
                const uint32_t ad = sb + (arow + mt * 16) * ROW_B + kb + acol;
                ldsm4(Ah[mt], ad);
                ldsm4(Al[mt], ad + COMP_B);
            }
            // Bh: term1 (Ah*Bh) + term2 (Al*Bh)
            #pragma unroll
            for (int bt = 0; bt < 4; bt++)
                ldsm4(B[bt], sb + 2*COMP_B + (brow + bt * 16) * ROW_B + kb + bcol);
            #pragma unroll
            for (int mt = 0; mt < 2; mt++)
                #pragma unroll
                for (int bt = 0; bt < 4; bt++) {
                    mma_bf16(acc[mt][2*bt],   Ah[mt], B[bt][0], B[bt][1]);
                    mma_bf16(acc[mt][2*bt+1], Ah[mt], B[bt][2], B[bt][3]);
                    mma_bf16(acc[mt][2*bt],   Al[mt], B[bt][0], B[bt][1]);
                    mma_bf16(acc[mt][2*bt+1], Al[mt], B[bt][2], B[bt][3]);
                }
            // Bl: term3 (Ah*Bl)
            #pragma unroll
            for (int bt = 0; bt < 4; bt++)
                ldsm4(B[bt], sb + 3*COMP_B + (brow + bt * 16) * ROW_B + kb + bcol);
            #pragma unroll
            for (int mt = 0; mt < 2; mt++)
                #pragma unroll
                for (int bt = 0; bt < 4; bt++) {
                    mma_bf16(acc[mt][2*bt],   Ah[mt], B[bt][0], B[bt][1]);
                    mma_bf16(acc[mt][2*bt+1], Ah[mt], B[bt][2], B[bt][3]);
                }
        }
        __syncthreads();
    }

    // ---- epilogue ----
    const int tg  = lane >> 2;
    const int tc2 = (lane & 3) * 2;
    const int h   = (n0 + wn * 64) >> 6;   // head fixed per warp

    #pragma unroll
    for (int mt = 0; mt < 2; mt++) {
        const int r0 = m0 + wm * 32 + mt * 16 + tg;
        const int r1 = r0 + 8;
        float gv0 = 1.f, gv1 = 1.f;
        if (G) {
            gv0 = gate[(((size_t)(r0 >> 9)) * NH + h) * LEN + (r0 & 511)];
            gv1 = gate[(((size_t)(r1 >> 9)) * NH + h) * LEN + (r1 & 511)];
        }
        #pragma unroll
        for (int nt = 0; nt < 8; nt++) {
            const int cn = n0 + wn * 64 + nt * 8 + tc2;
            const float bs0 = bias[cn], bs1 = bias[cn + 1];
            const float v00 = (acc[mt][nt][0] + bs0) * gv0;
            const float v01 = (acc[mt][nt][1] + bs1) * gv0;
            const float v10 = (acc[mt][nt][2] + bs0) * gv1;
            const float v11 = (acc[mt][nt][3] + bs1) * gv1;
            if (OM == 0) {
                if (r0 < M) *(float2*)&Cf[(size_t)r0 * N + cn] = make_float2(v00, v01);
                if (r1 < M) *(float2*)&Cf[(size_t)r1 * N + cn] = make_float2(v10, v11);
            } else {
                __nv_bfloat162 H0, L0, H1, L1;
                H0.x = __float2bfloat16(v00); H0.y = __float2bfloat16(v01);
                L0.x = __float2bfloat16(v00 - __bfloat162float(H0.x));
                L0.y = __float2bfloat16(v01 - __bfloat162float(H0.y));
                H1.x = __float2bfloat16(v10); H1.y = __float2bfloat16(v11);
                L1.x = __float2bfloat16(v10 - __bfloat162float(H1.x));
                L1.y = __float2bfloat16(v11 - __bfloat162float(H1.y));
                if (r0 < M) {
                    *(__nv_bfloat162*)(Chi + (size_t)r0 * N + cn) = H0;
                    *(__nv_bfloat162*)(Clo + (size_t)r0 * N + cn) = L0;
                }
                if (r1 < M) {
                    *(__nv_bfloat162*)(Chi + (size_t)r1 * N + cn) = H1;
                    *(__nv_bfloat162*)(Clo + (size_t)r1 * N + cn) = L1;
                }
            }
        }
    }
}

// ============================================================================
// scores[b][h][j] = dot64(qp[b,h,:], kp[b,j,h,:]) / 8    (reads fp32 g_kpq)
// ============================================================================
__global__ __launch_bounds__(512)
void scores_kernel(float* __restrict__ scores)
{
    const int b  = blockIdx.x;
    const int jq = blockIdx.y;
    __shared__ float qp_s[DIM];
    const int t = threadIdx.x;
    for (int i = t; i < DIM; i += 512) qp_s[i] = g_kpq[(size_t)b * DIM + i];
    __syncthreads();

    const int h = t >> 5;
    const int lane = t & 31;
    const float4* qv = (const float4*)&qp_s[h * DKH];

    #pragma unroll
    for (int jj = 0; jj < 4; jj++) {
        const int j = jq * 128 + jj * 32 + lane;
        const float4* kv =
            (const float4*)(g_kpq + (size_t)(64 + b * LEN + j) * DIM + h * DKH);
        float s = 0.f;
        #pragma unroll
        for (int d = 0; d < 16; d++) {
            float4 a = qv[d];
            float4 c = kv[d];
            s = fmaf(a.x, c.x, s); s = fmaf(a.y, c.y, s);
            s = fmaf(a.z, c.z, s); s = fmaf(a.w, c.w, s);
        }
        scores[((size_t)b * NH + h) * LEN + j] = s * 0.125f;
    }
}

// ============================================================================
// qe_score -> back gate (sigmoid) + fcw output
// ============================================================================
__global__ __launch_bounds__(256)
void qe_kernel(const float* __restrict__ qe,
               const float* __restrict__ cw,
               const float* __restrict__ lambdas,
               const float* __restrict__ scores,
               float* __restrict__ back,
               float* __restrict__ fcw)
{
    __shared__ float sc_s[NH][513];
    __shared__ float qe_t[64][33];

    const int b  = blockIdx.x;
    const int i0 = blockIdx.y * 64;
    const int t  = threadIdx.x;

    for (int i = t; i < NH * LEN; i += 256)
        sc_s[i >> 9][i & 511] = scores[(size_t)b * NH * LEN + i];

    const int il = t >> 2;
    const int hg = t & 3;
    float acc[4] = {0.f, 0.f, 0.f, 0.f};

    for (int jc = 0; jc < 16; jc++) {
        __syncthreads();
        #pragma unroll
        for (int p = 0; p < 8; p++) {
            const int f = t + p * 256;
            const int r = f >> 5, c = f & 31;
            qe_t[r][c] = qe[((size_t)b * LEN + i0 + r) * LEN + jc * 32 + c];
        }
        __syncthreads();
        #pragma unroll
        for (int jj = 0; jj < 32; jj++) {
            const float qv = qe_t[il][jj];
            const int j = jc * 32 + jj;
            acc[0] = fmaf(qv, sc_s[hg     ][j], acc[0]);
            acc[1] = fmaf(qv, sc_s[hg + 4 ][j], acc[1]);
            acc[2] = fmaf(qv, sc_s[hg + 8 ][j], acc[2]);
            acc[3] = fmaf(qv, sc_s[hg + 12][j], acc[3]);
        }
    }

    const float c_w = cw[(size_t)b * LEN + i0 + il];
    #pragma unroll
    for (int c = 0; c < 4; c++) {
        const int h = hg + 4 * c;
        const float lam = lambdas[h];
        const float x = acc[c];
        const float z = lam * c_w + (1.f - lam) * x;
        const float bk = 1.f / (1.f + expf(-z));
        back[((size_t)b * NH + h) * LEN + i0 + il] = bk;
        if (h == 0) fcw[(size_t)b * LEN + i0 + il] = x;
    }
}

// ============================================================================
// launch
// ============================================================================
static inline void launch_split(const float* src, __nv_bfloat16* hi, __nv_bfloat16* lo, size_t n) {
    size_t n4 = n / 4;
    int blocks = (int)((n4 + 255) / 256);
    split_kernel<<<blocks, 256>>>((const float4*)src, hi, lo, n4);
}

extern "C" void kernel_launch(void* const* d_in, const int* in_sizes, int n_in,
                              void* d_out, int out_size)
{
    const float* q   = (const float*)d_in[0];
    const float* k   = (const float*)d_in[1];
    const float* v   = (const float*)d_in[2];
    const float* cw  = (const float*)d_in[3];
    const float* qe  = (const float*)d_in[4];
    const float* Wq  = (const float*)d_in[5];
    const float* bq  = (const float*)d_in[6];
    const float* Wv  = (const float*)d_in[7];
    const float* bv  = (const float*)d_in[8];
    const float* Wo  = (const float*)d_in[9];
    const float* bo  = (const float*)d_in[10];
    const float* lam = (const float*)d_in[11];

    float* out_main = (float*)d_out;
    float* out_fcw  = (float*)d_out + OUT_MAIN_ELEMS;

    __nv_bfloat16 *qk_hi, *qk_lo, *v_hi, *v_lo, *wq_hi, *wq_lo, *wv_hi, *wv_lo, *wo_hi, *wo_lo, *c_hi, *c_lo;
    float *kpq, *scores, *back;
    cudaGetSymbolAddress((void**)&qk_hi, g_qk_hi);  cudaGetSymbolAddress((void**)&qk_lo, g_qk_lo);
    cudaGetSymbolAddress((void**)&v_hi,  g_v_hi);   cudaGetSymbolAddress((void**)&v_lo,  g_v_lo);
    cudaGetSymbolAddress((void**)&wq_hi, g_wq_hi);  cudaGetSymbolAddress((void**)&wq_lo, g_wq_lo);
    cudaGetSymbolAddress((void**)&wv_hi, g_wv_hi);  cudaGetSymbolAddress((void**)&wv_lo, g_wv_lo);
    cudaGetSymbolAddress((void**)&wo_hi, g_wo_hi);  cudaGetSymbolAddress((void**)&wo_lo, g_wo_lo);
    cudaGetSymbolAddress((void**)&c_hi,  g_c_hi);   cudaGetSymbolAddress((void**)&c_lo,  g_c_lo);
    cudaGetSymbolAddress((void**)&kpq,    g_kpq);
    cudaGetSymbolAddress((void**)&scores, g_scores);
    cudaGetSymbolAddress((void**)&back,   g_back);

    cudaFuncSetAttribute(gemm_mma<0, false>, cudaFuncAttributeMaxDynamicSharedMemorySize, 2 * STAGE_B);
    cudaFuncSetAttribute(gemm_mma<1, true>,  cudaFuncAttributeMaxDynamicSharedMemorySize, 2 * STAGE_B);

    // conversions
    launch_split(q,  qk_hi,                     qk_lo,                     (size_t)64 * 2048);
    launch_split(k,  qk_hi + (size_t)64 * 2048, qk_lo + (size_t)64 * 2048, (size_t)M_KV * 2048);
    launch_split(v,  v_hi,  v_lo,  (size_t)M_KV * 3072);
    launch_split(Wq, wq_hi, wq_lo, (size_t)1024 * 2048);
    launch_split(Wv, wv_hi, wv_lo, (size_t)1024 * 3072);
    launch_split(Wo, wo_hi, wo_lo, (size_t)1024 * 1024);

    // 1. [q;k] @ Wq^T + bq -> g_kpq (fp32)
    gemm_mma<0, false><<<dim3(8, 257), 256, 2 * STAGE_B>>>(
        qk_hi, qk_lo, wq_hi, wq_lo, bq, nullptr,
        kpq, nullptr, nullptr, M_KQ, DIM, 2 * DIM);

    // 2. scores
    scores_kernel<<<dim3(BSZ, 4), 512>>>(scores);

    // 3. qe_score -> gate + fcw
    qe_kernel<<<dim3(BSZ, 8), 256>>>(qe, cw, lam, scores, back, out_fcw);

    // 4. v @ Wv^T + bv, gated -> concat (bf16 hi/lo, split in epilogue)
    gemm_mma<1, true><<<dim3(8, 256), 256, 2 * STAGE_B>>>(
        v_hi, v_lo, wv_hi, wv_lo, bv, back,
        nullptr, c_hi, c_lo, M_KV, DIM, 3 * DIM);

    // 5. concat @ Wo^T + bo -> main output (fp32)
    gemm_mma<0, false><<<dim3(8, 256), 256, 2 * STAGE_B>>>(
        c_hi, c_lo, wo_hi, wo_lo, bo, nullptr,
        out_main, nullptr, nullptr, M_KV, DIM, DIM);
}

// round 4
// speedup vs baseline: 3.5869x; 1.4130x over previous
#include <cuda_runtime.h>
#include <cuda_fp16.h>
#include <cstdint>
#include <cstddef>
#include <math.h>

// Problem constants
#define BSZ 64
#define LEN 512
#define DIM 1024
#define NH  16
#define DKH 64

#define M_KQ 32832           // 64 q rows + 64*512 k rows
#define M_KQ_PAD 32896       // 257 * 128
#define M_KV 32768
#define OUT_MAIN_ELEMS ((size_t)BSZ*LEN*DIM)

// ---------------------------------------------------------------------------
// scratch (__device__ globals)
// ---------------------------------------------------------------------------
__device__ __half g_qk_hi[(size_t)M_KQ_PAD * 2048];
__device__ __half g_qk_lo[(size_t)M_KQ_PAD * 2048];
__device__ __half g_v_hi[(size_t)M_KV * 3072];
__device__ __half g_wq_hi[1024 * 2048];
__device__ __half g_wq_lo[1024 * 2048];
__device__ __half g_wv_hi[1024 * 3072];
__device__ __half g_wo_hi[1024 * 1024];
__device__ __half g_wo_lo[1024 * 1024];
__device__ __half g_c_hi[(size_t)M_KV * DIM];
__device__ __half g_c_lo[(size_t)M_KV * DIM];
__device__ float g_kpq[(size_t)M_KQ * DIM];
__device__ float g_scores[(size_t)BSZ * NH * LEN];
__device__ float g_back[(size_t)BSZ * NH * LEN];

// ---------------------------------------------------------------------------
// PTX helpers (base sm_103 target — portable mma.sync / cp.async / ldmatrix)
// ---------------------------------------------------------------------------
__device__ __forceinline__ uint32_t smem_u32(const void* p) {
    uint32_t a;
    asm("{ .reg .u64 t; cvta.to.shared.u64 t, %1; cvt.u32.u64 %0, t; }" : "=r"(a) : "l"(p));
    return a;
}
__device__ __forceinline__ void cpa16(uint32_t s, const void* g) {
    asm volatile("cp.async.cg.shared.global [%0], [%1], 16;" :: "r"(s), "l"(g));
}
__device__ __forceinline__ void cp_commit() {
    asm volatile("cp.async.commit_group;");
}
template<int N> __device__ __forceinline__ void cp_wait() {
    asm volatile("cp.async.wait_group %0;" :: "n"(N));
}
__device__ __forceinline__ void ldsm4(uint32_t* r, uint32_t a) {
    asm volatile("ldmatrix.sync.aligned.m8n8.x4.shared.b16 {%0,%1,%2,%3}, [%4];"
                 : "=r"(r[0]), "=r"(r[1]), "=r"(r[2]), "=r"(r[3]) : "r"(a));
}
__device__ __forceinline__ void mma_f16(float* d, const uint32_t* a, uint32_t b0, uint32_t b1) {
    asm volatile(
        "mma.sync.aligned.m16n8k16.row.col.f32.f16.f16.f32 "
        "{%0,%1,%2,%3}, {%4,%5,%6,%7}, {%8,%9}, {%0,%1,%2,%3};"
        : "+f"(d[0]), "+f"(d[1]), "+f"(d[2]), "+f"(d[3])
        : "r"(a[0]), "r"(a[1]), "r"(a[2]), "r"(a[3]), "r"(b0), "r"(b1));
}

// ---------------------------------------------------------------------------
// fp32 -> fp16 hi(/lo) split conversion
// ---------------------------------------------------------------------------
struct hf4 { __half a, b, c, d; };

template<bool LO>
__global__ void split_kernel(const float4* __restrict__ src,
                             __half* __restrict__ hi,
                             __half* __restrict__ lo, size_t n4) {
    size_t i = (size_t)blockIdx.x * blockDim.x + threadIdx.x;
    if (i >= n4) return;
    float4 v = src[i];
    __half h0 = __float2half_rn(v.x);
    __half h1 = __float2half_rn(v.y);
    __half h2 = __float2half_rn(v.z);
    __half h3 = __float2half_rn(v.w);
    hf4 H = {h0, h1, h2, h3};
    *(hf4*)(hi + i * 4) = H;
    if (LO) {
        hf4 L = {__float2half_rn(v.x - __half2float(h0)),
                 __float2half_rn(v.y - __half2float(h1)),
                 __float2half_rn(v.z - __half2float(h2)),
                 __float2half_rn(v.w - __half2float(h3))};
        *(hf4*)(lo + i * 4) = L;
    }
}

// ---------------------------------------------------------------------------
// mma.sync split-fp16 GEMM:  C[m][n] = sum_k A[m][k]*B[n][k] + bias[n]
// CTA 128x128, BK=32, 256 thr (8 warps, warp tile 32x64), multi-stage cp.async.
// TERMS: 3 = split (Ah*Bh + Al*Bh + Ah*Bl), 1 = single-pass.
// OM: 0 = fp32 out, 1 = fp16 hi/lo split out.   G: gate multiply.
// ---------------------------------------------------------------------------
#define COMP_B   10240
#define ROW_B    80

template<int TERMS, int STAGES, int OM, bool G>
__global__ __launch_bounds__(256, 2)
void gemm_mma(const __half* __restrict__ Ahi, const __half* __restrict__ Alo,
              const __half* __restrict__ Bhi, const __half* __restrict__ Blo,
              const float* __restrict__ bias, const float* __restrict__ gate,
              float* __restrict__ Cf,
              __half* __restrict__ Chi, __half* __restrict__ Clo,
              int M, int N, int K)
{
    constexpr int NCOMP   = (TERMS == 3) ? 4 : 2;
    constexpr int STAGE_B = NCOMP * COMP_B;
    constexpr int OFF_B   = (TERMS == 3) ? 2 * COMP_B : COMP_B;

    extern __shared__ __align__(16) char dsm[];
    const int tid  = threadIdx.x;
    const int wid  = tid >> 5;
    const int lane = tid & 31;
    const int wm = wid & 3;       // warp m index (32 rows each)
    const int wn = wid >> 2;      // warp n index (64 cols each)
    const int n0 = blockIdx.x * 128;
    const int m0 = blockIdx.y * 128;
    const uint32_t sbase = smem_u32(dsm);

    const __half* aH = Ahi + (size_t)m0 * K;
    const __half* aL = (TERMS == 3) ? (Alo + (size_t)m0 * K) : aH;
    const __half* bH = Bhi + (size_t)n0 * K;
    const __half* bL = (TERMS == 3) ? (Blo + (size_t)n0 * K) : bH;

    // per-thread cp.async slots: idx = j*256+tid -> row=idx>>2, seg=idx&3
    const int r_0 = tid >> 2,       r_1 = (256 + tid) >> 2;
    const int s_0 = (tid & 3) * 8,  s_1 = ((256 + tid) & 3) * 8;   // k-offset (halves)

    float acc[2][8][4];
    #pragma unroll
    for (int a = 0; a < 2; a++)
        #pragma unroll
        for (int b = 0; b < 8; b++)
            #pragma unroll
            for (int c = 0; c < 4; c++) acc[a][b][c] = 0.f;

    const int NC = K >> 5;   // BK=32 chunks

    auto issue = [&](int c) {
        const int kc = c << 5;
        const uint32_t sb = sbase + (uint32_t)(c % STAGES) * STAGE_B;
        cpa16(sb + r_0*ROW_B + s_0*2, aH + (size_t)r_0 * K + kc + s_0);
        cpa16(sb + r_1*ROW_B + s_1*2, aH + (size_t)r_1 * K + kc + s_1);
        if (TERMS == 3) {
            cpa16(sb + COMP_B + r_0*ROW_B + s_0*2, aL + (size_t)r_0 * K + kc + s_0);
            cpa16(sb + COMP_B + r_1*ROW_B + s_1*2, aL + (size_t)r_1 * K + kc + s_1);
        }
        cpa16(sb + OFF_B + r_0*ROW_B + s_0*2, bH + (size_t)r_0 * K + kc + s_0);
        cpa16(sb + OFF_B + r_1*ROW_B + s_1*2, bH + (size_t)r_1 * K + kc + s_1);
        if (TERMS == 3) {
            cpa16(sb + OFF_B + COMP_B + r_0*ROW_B + s_0*2, bL + (size_t)r_0 * K + kc + s_0);
            cpa16(sb + OFF_B + COMP_B + r_1*ROW_B + s_1*2, bL + (size_t)r_1 * K + kc + s_1);
        }
        cp_commit();
    };

    #pragma unroll
    for (int s = 0; s < STAGES - 1; s++) issue(s);

    const int arow = wm * 32 + (lane & 15);
    const int acol = (lane >> 4) * 16;                         // bytes within 32B k-half
    const int brow = wn * 64 + ((lane >> 4) << 3) + (lane & 7);
    const int bcol = ((lane >> 3) & 1) * 16;                   // bytes

    for (int c = 0; c < NC; c++) {
        // wait so that group c is complete (outstanding newer groups = min(STAGES-2, NC-1-c))
        if (c + STAGES - 2 < NC) cp_wait<STAGES - 2>();
        else                     cp_wait<0>();
        __syncthreads();
        if (c + STAGES - 1 < NC) issue(c + STAGES - 1);

        const uint32_t sb = sbase + (uint32_t)(c % STAGES) * STAGE_B;

        #pragma unroll
        for (int ks = 0; ks < 2; ks++) {
            const uint32_t kb = ks * 32;   // byte offset of k16 step
            uint32_t Ah[2][4], Al[2][4], Bh[4][4], Bl[4][4];
            #pragma unroll
            for (int mt = 0; mt < 2; mt++) {
                const uint32_t ad = sb + (arow + mt * 16) * ROW_B + kb + acol;
                ldsm4(Ah[mt], ad);
                if (TERMS == 3) ldsm4(Al[mt], ad + COMP_B);
            }
            #pragma unroll
            for (int bt = 0; bt < 4; bt++) {
                const uint32_t bd = sb + OFF_B + (brow + bt * 16) * ROW_B + kb + bcol;
                ldsm4(Bh[bt], bd);
                if (TERMS == 3) ldsm4(Bl[bt], bd + COMP_B);
            }
            // pass 1: Ah*Bh  (16 mmas, all distinct accumulators)
            #pragma unroll
            for (int mt = 0; mt < 2; mt++)
                #pragma unroll
                for (int bt = 0; bt < 4; bt++) {
                    mma_f16(acc[mt][2*bt],   Ah[mt], Bh[bt][0], Bh[bt][1]);
                    mma_f16(acc[mt][2*bt+1], Ah[mt], Bh[bt][2], Bh[bt][3]);
                }
            if (TERMS == 3) {
                // pass 2: Al*Bh
                #pragma unroll
                for (int mt = 0; mt < 2; mt++)
                    #pragma unroll
                    for (int bt = 0; bt < 4; bt++) {
                        mma_f16(acc[mt][2*bt],   Al[mt], Bh[bt][0], Bh[bt][1]);
                        mma_f16(acc[mt][2*bt+1], Al[mt], Bh[bt][2], Bh[bt][3]);
                    }
                // pass 3: Ah*Bl
                #pragma unroll
                for (int mt = 0; mt < 2; mt++)
                    #pragma unroll
                    for (int bt = 0; bt < 4; bt++) {
                        mma_f16(acc[mt][2*bt],   Ah[mt], Bl[bt][0], Bl[bt][1]);
                        mma_f16(acc[mt][2*bt+1], Ah[mt], Bl[bt][2], Bl[bt][3]);
                    }
            }
        }
    }

    // ---- epilogue ----
    const int tg  = lane >> 2;
    const int tc2 = (lane & 3) * 2;
    const int h   = (n0 + wn * 64) >> 6;   // head fixed per warp

    #pragma unroll
    for (int mt = 0; mt < 2; mt++) {
        const int r0 = m0 + wm * 32 + mt * 16 + tg;
        const int r1 = r0 + 8;
        float gv0 = 1.f, gv1 = 1.f;
        if (G) {
            gv0 = gate[(((size_t)(r0 >> 9)) * NH + h) * LEN + (r0 & 511)];
            gv1 = gate[(((size_t)(r1 >> 9)) * NH + h) * LEN + (r1 & 511)];
        }
        #pragma unroll
        for (int nt = 0; nt < 8; nt++) {
            const int cn = n0 + wn * 64 + nt * 8 + tc2;
            const float bs0 = bias[cn], bs1 = bias[cn + 1];
            const float v00 = (acc[mt][nt][0] + bs0) * gv0;
            const float v01 = (acc[mt][nt][1] + bs1) * gv0;
            const float v10 = (acc[mt][nt][2] + bs0) * gv1;
            const float v11 = (acc[mt][nt][3] + bs1) * gv1;
            if (OM == 0) {
                if (r0 < M) *(float2*)&Cf[(size_t)r0 * N + cn] = make_float2(v00, v01);
                if (r1 < M) *(float2*)&Cf[(size_t)r1 * N + cn] = make_float2(v10, v11);
            } else {
                __half2 H0, L0, H1, L1;
                H0.x = __float2half_rn(v00); H0.y = __float2half_rn(v01);
                L0.x = __float2half_rn(v00 - __half2float(H0.x));
                L0.y = __float2half_rn(v01 - __half2float(H0.y));
                H1.x = __float2half_rn(v10); H1.y = __float2half_rn(v11);
                L1.x = __float2half_rn(v10 - __half2float(H1.x));
                L1.y = __float2half_rn(v11 - __half2float(H1.y));
                if (r0 < M) {
                    *(__half2*)(Chi + (size_t)r0 * N + cn) = H0;
                    *(__half2*)(Clo + (size_t)r0 * N + cn) = L0;
                }
                if (r1 < M) {
                    *(__half2*)(Chi + (size_t)r1 * N + cn) = H1;
                    *(__half2*)(Clo + (size_t)r1 * N + cn) = L1;
                }
            }
        }
    }
}

// ============================================================================
// scores[b][h][j] = dot64(qp[b,h,:], kp[b,j,h,:]) / 8    (reads fp32 g_kpq)
// ============================================================================
__global__ __launch_bounds__(512)
void scores_kernel(float* __restrict__ scores)
{
    const int b  = blockIdx.x;
    const int jq = blockIdx.y;
    __shared__ float qp_s[DIM];
    const int t = threadIdx.x;
    for (int i = t; i < DIM; i += 512) qp_s[i] = g_kpq[(size_t)b * DIM + i];
    __syncthreads();

    const int h = t >> 5;
    const int lane = t & 31;
    const float4* qv = (const float4*)&qp_s[h * DKH];

    #pragma unroll
    for (int jj = 0; jj < 4; jj++) {
        const int j = jq * 128 + jj * 32 + lane;
        const float4* kv =
            (const float4*)(g_kpq + (size_t)(64 + b * LEN + j) * DIM + h * DKH);
        float s = 0.f;
        #pragma unroll
        for (int d = 0; d < 16; d++) {
            float4 a = qv[d];
            float4 c = kv[d];
            s = fmaf(a.x, c.x, s); s = fmaf(a.y, c.y, s);
            s = fmaf(a.z, c.z, s); s = fmaf(a.w, c.w, s);
        }
        scores[((size_t)b * NH + h) * LEN + j] = s * 0.125f;
    }
}

// ============================================================================
// qe_score -> back gate (sigmoid) + fcw output
// ============================================================================
__global__ __launch_bounds__(256)
void qe_kernel(const float* __restrict__ qe,
               const float* __restrict__ cw,
               const float* __restrict__ lambdas,
               const float* __restrict__ scores,
               float* __restrict__ back,
               float* __restrict__ fcw)
{
    __shared__ float sc_s[NH][513];
    __shared__ float qe_t[64][33];

    const int b  = blockIdx.x;
    const int i0 = blockIdx.y * 64;
    const int t  = threadIdx.x;

    for (int i = t; i < NH * LEN; i += 256)
        sc_s[i >> 9][i & 511] = scores[(size_t)b * NH * LEN + i];

    const int il = t >> 2;
    const int hg = t & 3;
    float acc[4] = {0.f, 0.f, 0.f, 0.f};

    for (int jc = 0; jc < 16; jc++) {
        __syncthreads();
        #pragma unroll
        for (int p = 0; p < 8; p++) {
            const int f = t + p * 256;
            const int r = f >> 5, c = f & 31;
            qe_t[r][c] = qe[((size_t)b * LEN + i0 + r) * LEN + jc * 32 + c];
        }
        __syncthreads();
        #pragma unroll
        for (int jj = 0; jj < 32; jj++) {
            const float qv = qe_t[il][jj];
            const int j = jc * 32 + jj;
            acc[0] = fmaf(qv, sc_s[hg     ][j], acc[0]);
            acc[1] = fmaf(qv, sc_s[hg + 4 ][j], acc[1]);
            acc[2] = fmaf(qv, sc_s[hg + 8 ][j], acc[2]);
            acc[3] = fmaf(qv, sc_s[hg + 12][j], acc[3]);
        }
    }

    const float c_w = cw[(size_t)b * LEN + i0 + il];
    #pragma unroll
    for (int c = 0; c < 4; c++) {
        const int h = hg + 4 * c;
        const float lam = lambdas[h];
        const float x = acc[c];
        const float z = lam * c_w + (1.f - lam) * x;
        const float bk = 1.f / (1.f + expf(-z));
        back[((size_t)b * NH + h) * LEN + i0 + il] = bk;
        if (h == 0) fcw[(size_t)b * LEN + i0 + il] = x;
    }
}

// ============================================================================
// launch
// ============================================================================
static inline void launch_split2(const float* src, __half* hi, __half* lo, size_t n) {
    size_t n4 = n / 4;
    int blocks = (int)((n4 + 255) / 256);
    split_kernel<true><<<blocks, 256>>>((const float4*)src, hi, lo, n4);
}
static inline void launch_split1(const float* src, __half* hi, size_t n) {
    size_t n4 = n / 4;
    int blocks = (int)((n4 + 255) / 256);
    split_kernel<false><<<blocks, 256>>>((const float4*)src, hi, nullptr, n4);
}

extern "C" void kernel_launch(void* const* d_in, const int* in_sizes, int n_in,
                              void* d_out, int out_size)
{
    const float* q   = (const float*)d_in[0];
    const float* k   = (const float*)d_in[1];
    const float* v   = (const float*)d_in[2];
    const float* cw  = (const float*)d_in[3];
    const float* qe  = (const float*)d_in[4];
    const float* Wq  = (const float*)d_in[5];
    const float* bq  = (const float*)d_in[6];
    const float* Wv  = (const float*)d_in[7];
    const float* bv  = (const float*)d_in[8];
    const float* Wo  = (const float*)d_in[9];
    const float* bo  = (const float*)d_in[10];
    const float* lam = (const float*)d_in[11];

    float* out_main = (float*)d_out;
    float* out_fcw  = (float*)d_out + OUT_MAIN_ELEMS;

    __half *qk_hi, *qk_lo, *v_hi, *wq_hi, *wq_lo, *wv_hi, *wo_hi, *wo_lo, *c_hi, *c_lo;
    float *kpq, *scores, *back;
    cudaGetSymbolAddress((void**)&qk_hi, g_qk_hi);  cudaGetSymbolAddress((void**)&qk_lo, g_qk_lo);
    cudaGetSymbolAddress((void**)&v_hi,  g_v_hi);
    cudaGetSymbolAddress((void**)&wq_hi, g_wq_hi);  cudaGetSymbolAddress((void**)&wq_lo, g_wq_lo);
    cudaGetSymbolAddress((void**)&wv_hi, g_wv_hi);
    cudaGetSymbolAddress((void**)&wo_hi, g_wo_hi);  cudaGetSymbolAddress((void**)&wo_lo, g_wo_lo);
    cudaGetSymbolAddress((void**)&c_hi,  g_c_hi);   cudaGetSymbolAddress((void**)&c_lo,  g_c_lo);
    cudaGetSymbolAddress((void**)&kpq,    g_kpq);
    cudaGetSymbolAddress((void**)&scores, g_scores);
    cudaGetSymbolAddress((void**)&back,   g_back);

    const int smem3 = 2 * 4 * COMP_B;   // 2 stages x 4 comps = 81920
    const int smem1 = 3 * 2 * COMP_B;   // 3 stages x 2 comps = 61440
    cudaFuncSetAttribute(gemm_mma<3, 2, 0, false>, cudaFuncAttributeMaxDynamicSharedMemorySize, smem3);
    cudaFuncSetAttribute(gemm_mma<1, 3, 1, true>,  cudaFuncAttributeMaxDynamicSharedMemorySize, smem1);

    // conversions (fp16 split; v / Wv need hi only — GEMM2 is single-pass)
    launch_split2(q,  qk_hi,                     qk_lo,                     (size_t)64 * 2048);
    launch_split2(k,  qk_hi + (size_t)64 * 2048, qk_lo + (size_t)64 * 2048, (size_t)M_KV * 2048);
    launch_split1(v,  v_hi,  (size_t)M_KV * 3072);
    launch_split2(Wq, wq_hi, wq_lo, (size_t)1024 * 2048);
    launch_split1(Wv, wv_hi, (size_t)1024 * 3072);
    launch_split2(Wo, wo_hi, wo_lo, (size_t)1024 * 1024);

    // 1. [q;k] @ Wq^T + bq -> g_kpq (fp32), 3-term fp16 (near-exact)
    gemm_mma<3, 2, 0, false><<<dim3(8, 257), 256, smem3>>>(
        qk_hi, qk_lo, wq_hi, wq_lo, bq, nullptr,
        kpq, nullptr, nullptr, M_KQ, DIM, 2 * DIM);

    // 2. scores
    scores_kernel<<<dim3(BSZ, 4), 512>>>(scores);

    // 3. qe_score -> gate + fcw
    qe_kernel<<<dim3(BSZ, 8), 256>>>(qe, cw, lam, scores, back, out_fcw);

    // 4. v @ Wv^T + bv, gated -> concat (fp16 hi/lo out), SINGLE-pass fp16
    gemm_mma<1, 3, 1, true><<<dim3(8, 256), 256, smem1>>>(
        v_hi, nullptr, wv_hi, nullptr, bv, back,
        nullptr, c_hi, c_lo, M_KV, DIM, 3 * DIM);

    // 5. concat @ Wo^T + bo -> main output (fp32), 3-term fp16
    gemm_mma<3, 2, 0, false><<<dim3(8, 256), 256, smem3>>>(
        c_hi, c_lo, wo_hi, wo_lo, bo, nullptr,
        out_main, nullptr, nullptr, M_KV, DIM, DIM);
}

// round 5
// speedup vs baseline: 5.5322x; 1.5423x over previous
#include <cuda_runtime.h>
#include <cuda_fp16.h>
#include <cstdint>
#include <cstddef>
#include <math.h>

// Problem constants
#define BSZ 64
#define LEN 512
#define DIM 1024
#define NH  16
#define DKH 64

#define M_KV 32768
#define OUT_MAIN_ELEMS ((size_t)BSZ*LEN*DIM)

// ---------------------------------------------------------------------------
// scratch (__device__ globals)
// ---------------------------------------------------------------------------
__device__ __half g_v_hi[(size_t)M_KV * 3072];
__device__ __half g_wv_hi[1024 * 3072];
__device__ __half g_wo_hi[1024 * 1024];
__device__ __half g_wo_lo[1024 * 1024];
__device__ __half g_c_hi[(size_t)M_KV * DIM];
__device__ __half g_c_lo[(size_t)M_KV * DIM];
__device__ float g_qp[(size_t)BSZ * DIM];            // q projections
__device__ float g_w[(size_t)BSZ * NH * 2048];       // folded query-side weights
__device__ float g_cbh[BSZ * NH];                    // qp . bq (per b,h)
__device__ float g_scores[(size_t)BSZ * NH * LEN];
__device__ float g_back[(size_t)BSZ * NH * LEN];

// ---------------------------------------------------------------------------
// PTX helpers (base sm_103 target — portable mma.sync / cp.async / ldmatrix)
// ---------------------------------------------------------------------------
__device__ __forceinline__ uint32_t smem_u32(const void* p) {
    uint32_t a;
    asm("{ .reg .u64 t; cvta.to.shared.u64 t, %1; cvt.u32.u64 %0, t; }" : "=r"(a) : "l"(p));
    return a;
}
__device__ __forceinline__ void cpa16(uint32_t s, const void* g) {
    asm volatile("cp.async.cg.shared.global [%0], [%1], 16;" :: "r"(s), "l"(g));
}
__device__ __forceinline__ void cp_commit() {
    asm volatile("cp.async.commit_group;");
}
template<int N> __device__ __forceinline__ void cp_wait() {
    asm volatile("cp.async.wait_group %0;" :: "n"(N));
}
__device__ __forceinline__ void ldsm4(uint32_t* r, uint32_t a) {
    asm volatile("ldmatrix.sync.aligned.m8n8.x4.shared.b16 {%0,%1,%2,%3}, [%4];"
                 : "=r"(r[0]), "=r"(r[1]), "=r"(r[2]), "=r"(r[3]) : "r"(a));
}
__device__ __forceinline__ void mma_f16(float* d, const uint32_t* a, uint32_t b0, uint32_t b1) {
    asm volatile(
        "mma.sync.aligned.m16n8k16.row.col.f32.f16.f16.f32 "
        "{%0,%1,%2,%3}, {%4,%5,%6,%7}, {%8,%9}, {%0,%1,%2,%3};"
        : "+f"(d[0]), "+f"(d[1]), "+f"(d[2]), "+f"(d[3])
        : "r"(a[0]), "r"(a[1]), "r"(a[2]), "r"(a[3]), "r"(b0), "r"(b1));
}

// ---------------------------------------------------------------------------
// fp32 -> fp16 hi(/lo) split conversion
// ---------------------------------------------------------------------------
struct hf4 { __half a, b, c, d; };

template<bool LO>
__global__ void split_kernel(const float4* __restrict__ src,
                             __half* __restrict__ hi,
                             __half* __restrict__ lo, size_t n4) {
    size_t i = (size_t)blockIdx.x * blockDim.x + threadIdx.x;
    if (i >= n4) return;
    float4 v = src[i];
    __half h0 = __float2half_rn(v.x);
    __half h1 = __float2half_rn(v.y);
    __half h2 = __float2half_rn(v.z);
    __half h3 = __float2half_rn(v.w);
    hf4 H = {h0, h1, h2, h3};
    *(hf4*)(hi + i * 4) = H;
    if (LO) {
        hf4 L = {__float2half_rn(v.x - __half2float(h0)),
                 __float2half_rn(v.y - __half2float(h1)),
                 __float2half_rn(v.z - __half2float(h2)),
                 __float2half_rn(v.w - __half2float(h3))};
        *(hf4*)(lo + i * 4) = L;
    }
}

// ============================================================================
// qp[b][j] = q[b,:] . Wq[j,:] + bq[j]        (fp32 exact)
// grid (16, 16): (4-batch group, 64-col chunk). 256 thr, 1 output each.
// ============================================================================
__global__ __launch_bounds__(256)
void qp_kernel(const float* __restrict__ q, const float* __restrict__ Wq,
               const float* __restrict__ bq, float* __restrict__ qp)
{
    __shared__ float q_s[4][2048];
    const int t  = threadIdx.x;
    const int bg = blockIdx.x;     // 4 batches
    const int jc = blockIdx.y;     // 64 cols

    #pragma unroll
    for (int p = 0; p < 8; p++) {
        const int f = t + p * 256;                 // 2048 float4-groups? no: 4*2048/4=2048 f4
        const float4 v = *(const float4*)(q + ((size_t)(bg * 4 + (f >> 9)) * 2048) + (f & 511) * 4);
        *(float4*)&q_s[f >> 9][(f & 511) * 4] = v;
    }
    __syncthreads();

    const int bl = t >> 6;
    const int j  = jc * 64 + (t & 63);
    const float4* wr = (const float4*)(Wq + (size_t)j * 2048);
    const float4* qr = (const float4*)q_s[bl];
    float s = 0.f;
    #pragma unroll 8
    for (int i = 0; i < 512; i++) {
        float4 a = qr[i], b = wr[i];
        s = fmaf(a.x, b.x, s); s = fmaf(a.y, b.y, s);
        s = fmaf(a.z, b.z, s); s = fmaf(a.w, b.w, s);
    }
    qp[(size_t)(bg * 4 + bl) * DIM + j] = s + bq[j];
}

// ============================================================================
// w[b][h][c] = sum_d qp[b][h*64+d] * Wq[h*64+d][c];  cbh[b][h] = qp[b,h,:].bq
// grid (16, 16): (4-batch group, head). 256 thr, 8 cols x 4 batches each.
// ============================================================================
__global__ __launch_bounds__(256)
void wfold_kernel(const float* __restrict__ qp, const float* __restrict__ Wq,
                  const float* __restrict__ bq,
                  float* __restrict__ w, float* __restrict__ cbh)
{
    __shared__ float qp_s[4][64];
    const int t  = threadIdx.x;
    const int bg = blockIdx.x;
    const int h  = blockIdx.y;

    if (t < 256) {
        const int bl = t >> 6, d = t & 63;
        qp_s[bl][d] = qp[(size_t)(bg * 4 + bl) * DIM + h * 64 + d];
    }
    __syncthreads();

    if (t < 4) {
        float s = 0.f;
        for (int d = 0; d < 64; d++) s = fmaf(qp_s[t][d], bq[h * 64 + d], s);
        cbh[(bg * 4 + t) * NH + h] = s;
    }

    #pragma unroll
    for (int cc = 0; cc < 8; cc++) {
        const int c = cc * 256 + t;
        float a0 = 0.f, a1 = 0.f, a2 = 0.f, a3 = 0.f;
        #pragma unroll 16
        for (int d = 0; d < 64; d++) {
            const float wv = Wq[(size_t)(h * 64 + d) * 2048 + c];
            a0 = fmaf(qp_s[0][d], wv, a0);
            a1 = fmaf(qp_s[1][d], wv, a1);
            a2 = fmaf(qp_s[2][d], wv, a2);
            a3 = fmaf(qp_s[3][d], wv, a3);
        }
        w[((size_t)(bg * 4 + 0) * NH + h) * 2048 + c] = a0;
        w[((size_t)(bg * 4 + 1) * NH + h) * 2048 + c] = a1;
        w[((size_t)(bg * 4 + 2) * NH + h) * 2048 + c] = a2;
        w[((size_t)(bg * 4 + 3) * NH + h) * 2048 + c] = a3;
    }
}

// ============================================================================
// scores[b][h][l] = (k[b,l,:] . w[b,h,:] + cbh[b,h]) / 8     (fp32 exact)
// grid (64, 4): (b, 128-row l chunk). 256 thr = (16 h) x (16 lg of 8 rows).
// ============================================================================
__global__ __launch_bounds__(256)
void scores_kernel(const float* __restrict__ k, const float* __restrict__ w,
                   const float* __restrict__ cbh, float* __restrict__ scores)
{
    __shared__ float k_s[64][129];     // [kk][l] transposed
    __shared__ float w_s[16][65];

    const int t  = threadIdx.x;
    const int b  = blockIdx.x;
    const int lc = blockIdx.y;
    const int h  = t & 15;
    const int lg = t >> 4;

    float acc[8];
    #pragma unroll
    for (int i = 0; i < 8; i++) acc[i] = 0.f;

    for (int kc = 0; kc < 2048; kc += 64) {
        __syncthreads();
        // load k chunk transposed: 128 rows x 64 cols
        #pragma unroll
        for (int p = 0; p < 8; p++) {
            const int f = t + p * 256;        // 2048 float4 slots
            const int row = f >> 4, c4 = (f & 15) * 4;
            const float4 v = *(const float4*)(k + ((size_t)(b * 512 + lc * 128 + row) * 2048) + kc + c4);
            k_s[c4 + 0][row] = v.x;
            k_s[c4 + 1][row] = v.y;
            k_s[c4 + 2][row] = v.z;
            k_s[c4 + 3][row] = v.w;
        }
        // load w chunk: 16 h x 64 cols
        {
            const int f = t;                   // 256 float4 slots = 16*16
            const int hh = f >> 4, c4 = (f & 15) * 4;
            const float4 v = *(const float4*)(w + ((size_t)(b * NH + hh) * 2048) + kc + c4);
            w_s[hh][c4 + 0] = v.x; w_s[hh][c4 + 1] = v.y;
            w_s[hh][c4 + 2] = v.z; w_s[hh][c4 + 3] = v.w;
        }
        __syncthreads();

        #pragma unroll 8
        for (int kk = 0; kk < 64; kk++) {
            const float wv = w_s[h][kk];
            #pragma unroll
            for (int i = 0; i < 8; i++)
                acc[i] = fmaf(k_s[kk][lg * 8 + i], wv, acc[i]);
        }
    }

    const float cv = cbh[b * NH + h];
    #pragma unroll
    for (int i = 0; i < 8; i++) {
        const int l = lc * 128 + lg * 8 + i;
        scores[((size_t)b * NH + h) * LEN + l] = (acc[i] + cv) * 0.125f;
    }
}

// ---------------------------------------------------------------------------
// mma.sync split-fp16 GEMM:  C[m][n] = sum_k A[m][k]*B[n][k] + bias[n]
// CTA 128x128, BK=32, 256 thr (8 warps, warp tile 32x64), multi-stage cp.async.
// TERMS: 3 = split (Ah*Bh + Al*Bh + Ah*Bl), 1 = single-pass.
// OM: 0 = fp32 out, 1 = fp16 hi/lo split out.   G: gate multiply.
// ---------------------------------------------------------------------------
#define COMP_B   10240
#define ROW_B    80

template<int TERMS, int STAGES, int OM, bool G>
__global__ __launch_bounds__(256, 2)
void gemm_mma(const __half* __restrict__ Ahi, const __half* __restrict__ Alo,
              const __half* __restrict__ Bhi, const __half* __restrict__ Blo,
              const float* __restrict__ bias, const float* __restrict__ gate,
              float* __restrict__ Cf,
              __half* __restrict__ Chi, __half* __restrict__ Clo,
              int M, int N, int K)
{
    constexpr int NCOMP   = (TERMS == 3) ? 4 : 2;
    constexpr int STAGE_B = NCOMP * COMP_B;
    constexpr int OFF_B   = (TERMS == 3) ? 2 * COMP_B : COMP_B;

    extern __shared__ __align__(16) char dsm[];
    const int tid  = threadIdx.x;
    const int wid  = tid >> 5;
    const int lane = tid & 31;
    const int wm = wid & 3;
    const int wn = wid >> 2;
    const int n0 = blockIdx.x * 128;
    const int m0 = blockIdx.y * 128;
    const uint32_t sbase = smem_u32(dsm);

    const __half* aH = Ahi + (size_t)m0 * K;
    const __half* aL = (TERMS == 3) ? (Alo + (size_t)m0 * K) : aH;
    const __half* bH = Bhi + (size_t)n0 * K;
    const __half* bL = (TERMS == 3) ? (Blo + (size_t)n0 * K) : bH;

    const int r_0 = tid >> 2,       r_1 = (256 + tid) >> 2;
    const int s_0 = (tid & 3) * 8,  s_1 = ((256 + tid) & 3) * 8;

    float acc[2][8][4];
    #pragma unroll
    for (int a = 0; a < 2; a++)
        #pragma unroll
        for (int b = 0; b < 8; b++)
            #pragma unroll
            for (int c = 0; c < 4; c++) acc[a][b][c] = 0.f;

    const int NC = K >> 5;

    auto issue = [&](int c) {
        const int kc = c << 5;
        const uint32_t sb = sbase + (uint32_t)(c % STAGES) * STAGE_B;
        cpa16(sb + r_0*ROW_B + s_0*2, aH + (size_t)r_0 * K + kc + s_0);
        cpa16(sb + r_1*ROW_B + s_1*2, aH + (size_t)r_1 * K + kc + s_1);
        if (TERMS == 3) {
            cpa16(sb + COMP_B + r_0*ROW_B + s_0*2, aL + (size_t)r_0 * K + kc + s_0);
            cpa16(sb + COMP_B + r_1*ROW_B + s_1*2, aL + (size_t)r_1 * K + kc + s_1);
        }
        cpa16(sb + OFF_B + r_0*ROW_B + s_0*2, bH + (size_t)r_0 * K + kc + s_0);
        cpa16(sb + OFF_B + r_1*ROW_B + s_1*2, bH + (size_t)r_1 * K + kc + s_1);
        if (TERMS == 3) {
            cpa16(sb + OFF_B + COMP_B + r_0*ROW_B + s_0*2, bL + (size_t)r_0 * K + kc + s_0);
            cpa16(sb + OFF_B + COMP_B + r_1*ROW_B + s_1*2, bL + (size_t)r_1 * K + kc + s_1);
        }
        cp_commit();
    };

    #pragma unroll
    for (int s = 0; s < STAGES - 1; s++) issue(s);

    const int arow = wm * 32 + (lane & 15);
    const int acol = (lane >> 4) * 16;
    const int brow = wn * 64 + ((lane >> 4) << 3) + (lane & 7);
    const int bcol = ((lane >> 3) & 1) * 16;

    for (int c = 0; c < NC; c++) {
        if (c + STAGES - 2 < NC) cp_wait<STAGES - 2>();
        else                     cp_wait<0>();
        __syncthreads();
        if (c + STAGES - 1 < NC) issue(c + STAGES - 1);

        const uint32_t sb = sbase + (uint32_t)(c % STAGES) * STAGE_B;

        #pragma unroll
        for (int ks = 0; ks < 2; ks++) {
            const uint32_t kb = ks * 32;
            uint32_t Ah[2][4], Al[2][4], Bh[4][4], Bl[4][4];
            #pragma unroll
            for (int mt = 0; mt < 2; mt++) {
                const uint32_t ad = sb + (arow + mt * 16) * ROW_B + kb + acol;
                ldsm4(Ah[mt], ad);
                if (TERMS == 3) ldsm4(Al[mt], ad + COMP_B);
            }
            #pragma unroll
            for (int bt = 0; bt < 4; bt++) {
                const uint32_t bd = sb + OFF_B + (brow + bt * 16) * ROW_B + kb + bcol;
                ldsm4(Bh[bt], bd);
                if (TERMS == 3) ldsm4(Bl[bt], bd + COMP_B);
            }
            #pragma unroll
            for (int mt = 0; mt < 2; mt++)
                #pragma unroll
                for (int bt = 0; bt < 4; bt++) {
                    mma_f16(acc[mt][2*bt],   Ah[mt], Bh[bt][0], Bh[bt][1]);
                    mma_f16(acc[mt][2*bt+1], Ah[mt], Bh[bt][2], Bh[bt][3]);
                }
            if (TERMS == 3) {
                #pragma unroll
                for (int mt = 0; mt < 2; mt++)
                    #pragma unroll
                    for (int bt = 0; bt < 4; bt++) {
                        mma_f16(acc[mt][2*bt],   Al[mt], Bh[bt][0], Bh[bt][1]);
                        mma_f16(acc[mt][2*bt+1], Al[mt], Bh[bt][2], Bh[bt][3]);
                    }
                #pragma unroll
                for (int mt = 0; mt < 2; mt++)
                    #pragma unroll
                    for (int bt = 0; bt < 4; bt++) {
                        mma_f16(acc[mt][2*bt],   Ah[mt], Bl[bt][0], Bl[bt][1]);
                        mma_f16(acc[mt][2*bt+1], Ah[mt], Bl[bt][2], Bl[bt][3]);
                    }
            }
        }
    }

    // ---- epilogue ----
    const int tg  = lane >> 2;
    const int tc2 = (lane & 3) * 2;
    const int h   = (n0 + wn * 64) >> 6;

    #pragma unroll
    for (int mt = 0; mt < 2; mt++) {
        const int r0 = m0 + wm * 32 + mt * 16 + tg;
        const int r1 = r0 + 8;
        float gv0 = 1.f, gv1 = 1.f;
        if (G) {
            gv0 = gate[(((size_t)(r0 >> 9)) * NH + h) * LEN + (r0 & 511)];
            gv1 = gate[(((size_t)(r1 >> 9)) * NH + h) * LEN + (r1 & 511)];
        }
        #pragma unroll
        for (int nt = 0; nt < 8; nt++) {
            const int cn = n0 + wn * 64 + nt * 8 + tc2;
            const float bs0 = bias[cn], bs1 = bias[cn + 1];
            const float v00 = (acc[mt][nt][0] + bs0) * gv0;
            const float v01 = (acc[mt][nt][1] + bs1) * gv0;
            const float v10 = (acc[mt][nt][2] + bs0) * gv1;
            const float v11 = (acc[mt][nt][3] + bs1) * gv1;
            if (OM == 0) {
                if (r0 < M) *(float2*)&Cf[(size_t)r0 * N + cn] = make_float2(v00, v01);
                if (r1 < M) *(float2*)&Cf[(size_t)r1 * N + cn] = make_float2(v10, v11);
            } else {
                __half2 H0, L0, H1, L1;
                H0.x = __float2half_rn(v00); H0.y = __float2half_rn(v01);
                L0.x = __float2half_rn(v00 - __half2float(H0.x));
                L0.y = __float2half_rn(v01 - __half2float(H0.y));
                H1.x = __float2half_rn(v10); H1.y = __float2half_rn(v11);
                L1.x = __float2half_rn(v10 - __half2float(H1.x));
                L1.y = __float2half_rn(v11 - __half2float(H1.y));
                if (r0 < M) {
                    *(__half2*)(Chi + (size_t)r0 * N + cn) = H0;
                    *(__half2*)(Clo + (size_t)r0 * N + cn) = L0;
                }
                if (r1 < M) {
                    *(__half2*)(Chi + (size_t)r1 * N + cn) = H1;
                    *(__half2*)(Clo + (size_t)r1 * N + cn) = L1;
                }
            }
        }
    }
}

// ============================================================================
// qe_score -> back gate (sigmoid) + fcw output
// ============================================================================
__global__ __launch_bounds__(256)
void qe_kernel(const float* __restrict__ qe,
               const float* __restrict__ cw,
               const float* __restrict__ lambdas,
               const float* __restrict__ scores,
               float* __restrict__ back,
               float* __restrict__ fcw)
{
    __shared__ float sc_s[NH][513];
    __shared__ float qe_t[64][33];

    const int b  = blockIdx.x;
    const int i0 = blockIdx.y * 64;
    const int t  = threadIdx.x;

    for (int i = t; i < NH * LEN; i += 256)
        sc_s[i >> 9][i & 511] = scores[(size_t)b * NH * LEN + i];

    const int il = t >> 2;
    const int hg = t & 3;
    float acc[4] = {0.f, 0.f, 0.f, 0.f};

    for (int jc = 0; jc < 16; jc++) {
        __syncthreads();
        #pragma unroll
        for (int p = 0; p < 8; p++) {
            const int f = t + p * 256;
            const int r = f >> 5, c = f & 31;
            qe_t[r][c] = qe[((size_t)b * LEN + i0 + r) * LEN + jc * 32 + c];
        }
        __syncthreads();
        #pragma unroll
        for (int jj = 0; jj < 32; jj++) {
            const float qv = qe_t[il][jj];
            const int j = jc * 32 + jj;
            acc[0] = fmaf(qv, sc_s[hg     ][j], acc[0]);
            acc[1] = fmaf(qv, sc_s[hg + 4 ][j], acc[1]);
            acc[2] = fmaf(qv, sc_s[hg + 8 ][j], acc[2]);
            acc[3] = fmaf(qv, sc_s[hg + 12][j], acc[3]);
        }
    }

    const float c_w = cw[(size_t)b * LEN + i0 + il];
    #pragma unroll
    for (int c = 0; c < 4; c++) {
        const int h = hg + 4 * c;
        const float lam = lambdas[h];
        const float x = acc[c];
        const float z = lam * c_w + (1.f - lam) * x;
        const float bk = 1.f / (1.f + expf(-z));
        back[((size_t)b * NH + h) * LEN + i0 + il] = bk;
        if (h == 0) fcw[(size_t)b * LEN + i0 + il] = x;
    }
}

// ============================================================================
// launch
// ============================================================================
static inline void launch_split2(const float* src, __half* hi, __half* lo, size_t n) {
    size_t n4 = n / 4;
    int blocks = (int)((n4 + 255) / 256);
    split_kernel<true><<<blocks, 256>>>((const float4*)src, hi, lo, n4);
}
static inline void launch_split1(const float* src, __half* hi, size_t n) {
    size_t n4 = n / 4;
    int blocks = (int)((n4 + 255) / 256);
    split_kernel<false><<<blocks, 256>>>((const float4*)src, hi, nullptr, n4);
}

extern "C" void kernel_launch(void* const* d_in, const int* in_sizes, int n_in,
                              void* d_out, int out_size)
{
    const float* q   = (const float*)d_in[0];
    const float* k   = (const float*)d_in[1];
    const float* v   = (const float*)d_in[2];
    const float* cw  = (const float*)d_in[3];
    const float* qe  = (const float*)d_in[4];
    const float* Wq  = (const float*)d_in[5];
    const float* bq  = (const float*)d_in[6];
    const float* Wv  = (const float*)d_in[7];
    const float* bv  = (const float*)d_in[8];
    const float* Wo  = (const float*)d_in[9];
    const float* bo  = (const float*)d_in[10];
    const float* lam = (const float*)d_in[11];

    float* out_main = (float*)d_out;
    float* out_fcw  = (float*)d_out + OUT_MAIN_ELEMS;

    __half *v_hi, *wv_hi, *wo_hi, *wo_lo, *c_hi, *c_lo;
    float *qp, *wvec, *cbh, *scores, *back;
    cudaGetSymbolAddress((void**)&v_hi,  g_v_hi);
    cudaGetSymbolAddress((void**)&wv_hi, g_wv_hi);
    cudaGetSymbolAddress((void**)&wo_hi, g_wo_hi);  cudaGetSymbolAddress((void**)&wo_lo, g_wo_lo);
    cudaGetSymbolAddress((void**)&c_hi,  g_c_hi);   cudaGetSymbolAddress((void**)&c_lo,  g_c_lo);
    cudaGetSymbolAddress((void**)&qp,    g_qp);
    cudaGetSymbolAddress((void**)&wvec,  g_w);
    cudaGetSymbolAddress((void**)&cbh,   g_cbh);
    cudaGetSymbolAddress((void**)&scores, g_scores);
    cudaGetSymbolAddress((void**)&back,   g_back);

    const int smem3 = 2 * 4 * COMP_B;   // 81920
    const int smem1 = 3 * 2 * COMP_B;   // 61440
    cudaFuncSetAttribute(gemm_mma<3, 2, 0, false>, cudaFuncAttributeMaxDynamicSharedMemorySize, smem3);
    cudaFuncSetAttribute(gemm_mma<1, 3, 1, true>,  cudaFuncAttributeMaxDynamicSharedMemorySize, smem1);

    // conversions (only v / Wv / Wo need fp16 forms now)
    launch_split1(v,  v_hi,  (size_t)M_KV * 3072);
    launch_split1(Wv, wv_hi, (size_t)1024 * 3072);
    launch_split2(Wo, wo_hi, wo_lo, (size_t)1024 * 1024);

    // 1. query-side folding (exact fp32): qp -> w,cbh -> scores
    qp_kernel<<<dim3(16, 16), 256>>>(q, Wq, bq, qp);
    wfold_kernel<<<dim3(16, 16), 256>>>(qp, Wq, bq, wvec, cbh);
    scores_kernel<<<dim3(BSZ, 4), 256>>>(k, wvec, cbh, scores);

    // 2. qe_score -> gate + fcw
    qe_kernel<<<dim3(BSZ, 8), 256>>>(qe, cw, lam, scores, back, out_fcw);

    // 3. v @ Wv^T + bv, gated -> concat (fp16 hi/lo out), single-pass fp16
    gemm_mma<1, 3, 1, true><<<dim3(8, 256), 256, smem1>>>(
        v_hi, nullptr, wv_hi, nullptr, bv, back,
        nullptr, c_hi, c_lo, M_KV, DIM, 3 * DIM);

    // 4. concat @ Wo^T + bo -> main output (fp32), 3-term fp16
    gemm_mma<3, 2, 0, false><<<dim3(8, 256), 256, smem3>>>(
        c_hi, c_lo, wo_hi, wo_lo, bo, nullptr,
        out_main, nullptr, nullptr, M_KV, DIM, DIM);
}

// round 6
// speedup vs baseline: 7.5774x; 1.3697x over previous
#include <cuda_runtime.h>
#include <cuda_fp16.h>
#include <cstdint>
#include <cstddef>
#include <math.h>

// Problem constants
#define BSZ 64
#define LEN 512
#define DIM 1024
#define NH  16
#define DKH 64

#define M_KV 32768
#define OUT_MAIN_ELEMS ((size_t)BSZ*LEN*DIM)

// ---------------------------------------------------------------------------
// scratch (__device__ globals)
// ---------------------------------------------------------------------------
__device__ __half g_v_hi[(size_t)M_KV * 3072];
__device__ __half g_wv_hi[1024 * 3072];
__device__ __half g_wo_hi[1024 * 1024];
__device__ __half g_c_hi[(size_t)M_KV * DIM];
__device__ float g_qp_part[(size_t)32 * BSZ * DIM];  // k-split partials
__device__ float g_qp[(size_t)BSZ * DIM];            // q projections
__device__ float g_w[(size_t)BSZ * NH * 2048];       // folded query-side weights
__device__ float g_cbh[BSZ * NH];                    // qp . bq (per b,h)
__device__ float g_scores[(size_t)BSZ * NH * LEN];
__device__ float g_back[(size_t)BSZ * NH * LEN];

// ---------------------------------------------------------------------------
// PTX helpers (base sm_103 target — portable mma.sync / cp.async / ldmatrix)
// ---------------------------------------------------------------------------
__device__ __forceinline__ uint32_t smem_u32(const void* p) {
    uint32_t a;
    asm("{ .reg .u64 t; cvta.to.shared.u64 t, %1; cvt.u32.u64 %0, t; }" : "=r"(a) : "l"(p));
    return a;
}
__device__ __forceinline__ void cpa16(uint32_t s, const void* g) {
    asm volatile("cp.async.cg.shared.global [%0], [%1], 16;" :: "r"(s), "l"(g));
}
__device__ __forceinline__ void cp_commit() {
    asm volatile("cp.async.commit_group;");
}
template<int N> __device__ __forceinline__ void cp_wait() {
    asm volatile("cp.async.wait_group %0;" :: "n"(N));
}
__device__ __forceinline__ void ldsm4(uint32_t* r, uint32_t a) {
    asm volatile("ldmatrix.sync.aligned.m8n8.x4.shared.b16 {%0,%1,%2,%3}, [%4];"
                 : "=r"(r[0]), "=r"(r[1]), "=r"(r[2]), "=r"(r[3]) : "r"(a));
}
__device__ __forceinline__ void mma_f16(float* d, const uint32_t* a, uint32_t b0, uint32_t b1) {
    asm volatile(
        "mma.sync.aligned.m16n8k16.row.col.f32.f16.f16.f32 "
        "{%0,%1,%2,%3}, {%4,%5,%6,%7}, {%8,%9}, {%0,%1,%2,%3};"
        : "+f"(d[0]), "+f"(d[1]), "+f"(d[2]), "+f"(d[3])
        : "r"(a[0]), "r"(a[1]), "r"(a[2]), "r"(a[3]), "r"(b0), "r"(b1));
}

// ---------------------------------------------------------------------------
// fp32 -> fp16 conversion (hi only)
// ---------------------------------------------------------------------------
struct hf4 { __half a, b, c, d; };

__global__ void split_kernel(const float4* __restrict__ src,
                             __half* __restrict__ hi, size_t n4) {
    size_t i = (size_t)blockIdx.x * blockDim.x + threadIdx.x;
    if (i >= n4) return;
    float4 v = src[i];
    hf4 H = {__float2half_rn(v.x), __float2half_rn(v.y),
             __float2half_rn(v.z), __float2half_rn(v.w)};
    *(hf4*)(hi + i * 4) = H;
}

// ============================================================================
// qp partials: part[kc][b][j] = sum_{k in chunk kc} q[b][k] * Wq[j][k]
// grid (8 jc, 32 kc), 256 thr. smem-tiled, batch-register-blocked.
// ============================================================================
__global__ __launch_bounds__(256)
void qp_part_kernel(const float* __restrict__ q, const float* __restrict__ Wq,
                    float* __restrict__ part)
{
    __shared__ float q_s[64][65];    // [b][kk]
    __shared__ float w_s[128][65];   // [jj][kk]
    const int t  = threadIdx.x;
    const int jc = blockIdx.x;
    const int kc = blockIdx.y;
    const int k0 = kc * 64;

    #pragma unroll
    for (int p = 0; p < 4; p++) {
        const int f = t + p * 256;               // 1024 float4 slots
        const int b = f >> 4, c4 = (f & 15) * 4;
        const float4 v = *(const float4*)(q + (size_t)b * 2048 + k0 + c4);
        q_s[b][c4+0] = v.x; q_s[b][c4+1] = v.y; q_s[b][c4+2] = v.z; q_s[b][c4+3] = v.w;
    }
    #pragma unroll
    for (int p = 0; p < 8; p++) {
        const int f = t + p * 256;               // 2048 float4 slots
        const int j = f >> 4, c4 = (f & 15) * 4;
        const float4 v = *(const float4*)(Wq + (size_t)(jc * 128 + j) * 2048 + k0 + c4);
        w_s[j][c4+0] = v.x; w_s[j][c4+1] = v.y; w_s[j][c4+2] = v.z; w_s[j][c4+3] = v.w;
    }
    __syncthreads();

    const int jj = t & 63;       // this thread: cols jj and jj+64
    const int bg = t >> 6;       // batch group: 16 batches
    float acc0[16], acc1[16];
    #pragma unroll
    for (int b = 0; b < 16; b++) { acc0[b] = 0.f; acc1[b] = 0.f; }

    #pragma unroll 4
    for (int kk = 0; kk < 64; kk++) {
        const float w0 = w_s[jj][kk];
        const float w1 = w_s[jj + 64][kk];
        #pragma unroll
        for (int b = 0; b < 16; b++) {
            const float qv = q_s[bg * 16 + b][kk];
            acc0[b] = fmaf(qv, w0, acc0[b]);
            acc1[b] = fmaf(qv, w1, acc1[b]);
        }
    }
    #pragma unroll
    for (int b = 0; b < 16; b++) {
        const size_t base = ((size_t)kc * 64 + bg * 16 + b) * DIM + jc * 128;
        part[base + jj]      = acc0[b];
        part[base + jj + 64] = acc1[b];
    }
}

// qp[b][j] = sum_kc part[kc][b][j] + bq[j]
__global__ __launch_bounds__(256)
void qp_reduce_kernel(const float* __restrict__ part, const float* __restrict__ bq,
                      float* __restrict__ qp)
{
    const int b = blockIdx.x;
    const int t = threadIdx.x;
    #pragma unroll
    for (int jj = 0; jj < 4; jj++) {
        const int j = jj * 256 + t;
        float s = 0.f;
        #pragma unroll 8
        for (int kc = 0; kc < 32; kc++)
            s += part[((size_t)kc * 64 + b) * DIM + j];
        qp[(size_t)b * DIM + j] = s + bq[j];
    }
}

// ============================================================================
// w[b][h][c] = sum_d qp[b][h*64+d] * Wq[h*64+d][c];  cbh[b][h] = qp[b,h,:].bq
// grid (16 h, 8 cc), 256 thr: thread = col c, 64 batch accumulators.
// ============================================================================
__global__ __launch_bounds__(256)
void wfold_kernel(const float* __restrict__ qp, const float* __restrict__ Wq,
                  const float* __restrict__ bq,
                  float* __restrict__ w, float* __restrict__ cbh)
{
    __shared__ float qp_s[64][65];
    __shared__ float bq_s[64];
    const int t  = threadIdx.x;
    const int h  = blockIdx.x;
    const int cc = blockIdx.y;

    #pragma unroll
    for (int p = 0; p < 4; p++) {
        const int f = t + p * 256;               // 1024 float4 slots
        const int b = f >> 4, d4 = (f & 15) * 4;
        const float4 v = *(const float4*)(qp + (size_t)b * DIM + h * 64 + d4);
        qp_s[b][d4+0] = v.x; qp_s[b][d4+1] = v.y; qp_s[b][d4+2] = v.z; qp_s[b][d4+3] = v.w;
    }
    if (t < 16) {
        const float4 v = *(const float4*)(bq + h * 64 + t * 4);
        bq_s[t*4+0] = v.x; bq_s[t*4+1] = v.y; bq_s[t*4+2] = v.z; bq_s[t*4+3] = v.w;
    }
    __syncthreads();

    if (cc == 0 && t < 64) {
        float s = 0.f;
        #pragma unroll 8
        for (int d = 0; d < 64; d++) s = fmaf(qp_s[t][d], bq_s[d], s);
        cbh[t * NH + h] = s;
    }

    const int c = cc * 256 + t;
    float acc[64];
    #pragma unroll
    for (int b = 0; b < 64; b++) acc[b] = 0.f;

    for (int d = 0; d < 64; d++) {
        const float wv = Wq[(size_t)(h * 64 + d) * 2048 + c];
        #pragma unroll
        for (int b = 0; b < 64; b++)
            acc[b] = fmaf(qp_s[b][d], wv, acc[b]);
    }
    #pragma unroll
    for (int b = 0; b < 64; b++)
        w[((size_t)b * NH + h) * 2048 + c] = acc[b];
}

// ============================================================================
// scores[b][h][l] = (k[b,l,:] . w[b,h,:] + cbh[b,h]) / 8     (fp32 exact)
// ============================================================================
__global__ __launch_bounds__(256)
void scores_kernel(const float* __restrict__ k, const float* __restrict__ w,
                   const float* __restrict__ cbh, float* __restrict__ scores)
{
    __shared__ float k_s[64][129];
    __shared__ float w_s[16][65];

    const int t  = threadIdx.x;
    const int b  = blockIdx.x;
    const int lc = blockIdx.y;
    const int h  = t & 15;
    const int lg = t >> 4;

    float acc[8];
    #pragma unroll
    for (int i = 0; i < 8; i++) acc[i] = 0.f;

    for (int kc = 0; kc < 2048; kc += 64) {
        __syncthreads();
        #pragma unroll
        for (int p = 0; p < 8; p++) {
            const int f = t + p * 256;
            const int row = f >> 4, c4 = (f & 15) * 4;
            const float4 v = *(const float4*)(k + ((size_t)(b * 512 + lc * 128 + row) * 2048) + kc + c4);
            k_s[c4 + 0][row] = v.x;
            k_s[c4 + 1][row] = v.y;
            k_s[c4 + 2][row] = v.z;
            k_s[c4 + 3][row] = v.w;
        }
        {
            const int f = t;
            const int hh = f >> 4, c4 = (f & 15) * 4;
            const float4 v = *(const float4*)(w + ((size_t)(b * NH + hh) * 2048) + kc + c4);
            w_s[hh][c4 + 0] = v.x; w_s[hh][c4 + 1] = v.y;
            w_s[hh][c4 + 2] = v.z; w_s[hh][c4 + 3] = v.w;
        }
        __syncthreads();

        #pragma unroll 8
        for (int kk = 0; kk < 64; kk++) {
            const float wv = w_s[h][kk];
            #pragma unroll
            for (int i = 0; i < 8; i++)
                acc[i] = fmaf(k_s[kk][lg * 8 + i], wv, acc[i]);
        }
    }

    const float cv = cbh[b * NH + h];
    #pragma unroll
    for (int i = 0; i < 8; i++) {
        const int l = lc * 128 + lg * 8 + i;
        scores[((size_t)b * NH + h) * LEN + l] = (acc[i] + cv) * 0.125f;
    }
}

// ---------------------------------------------------------------------------
// mma.sync fp16 GEMM:  C[m][n] = sum_k A[m][k]*B[n][k] + bias[n]
// CTA 128x128, BK=32, 256 thr (8 warps, warp tile 32x64), 3-stage cp.async.
// OM: 0 = fp32 out, 1 = fp16 out.   G: gate multiply.
// ---------------------------------------------------------------------------
#define COMP_B   10240
#define ROW_B    80

template<int STAGES, int OM, bool G>
__global__ __launch_bounds__(256, 2)
void gemm_mma(const __half* __restrict__ Ahi,
              const __half* __restrict__ Bhi,
              const float* __restrict__ bias, const float* __restrict__ gate,
              float* __restrict__ Cf, __half* __restrict__ Chi,
              int M, int N, int K)
{
    constexpr int STAGE_B = 2 * COMP_B;
    constexpr int OFF_B   = COMP_B;

    extern __shared__ __align__(16) char dsm[];
    const int tid  = threadIdx.x;
    const int wid  = tid >> 5;
    const int lane = tid & 31;
    const int wm = wid & 3;
    const int wn = wid >> 2;
    const int n0 = blockIdx.x * 128;
    const int m0 = blockIdx.y * 128;
    const uint32_t sbase = smem_u32(dsm);

    const __half* aH = Ahi + (size_t)m0 * K;
    const __half* bH = Bhi + (size_t)n0 * K;

    const int r_0 = tid >> 2,       r_1 = (256 + tid) >> 2;
    const int s_0 = (tid & 3) * 8,  s_1 = ((256 + tid) & 3) * 8;

    float acc[2][8][4];
    #pragma unroll
    for (int a = 0; a < 2; a++)
        #pragma unroll
        for (int b = 0; b < 8; b++)
            #pragma unroll
            for (int c = 0; c < 4; c++) acc[a][b][c] = 0.f;

    const int NC = K >> 5;

    auto issue = [&](int c) {
        const int kc = c << 5;
        const uint32_t sb = sbase + (uint32_t)(c % STAGES) * STAGE_B;
        cpa16(sb + r_0*ROW_B + s_0*2, aH + (size_t)r_0 * K + kc + s_0);
        cpa16(sb + r_1*ROW_B + s_1*2, aH + (size_t)r_1 * K + kc + s_1);
        cpa16(sb + OFF_B + r_0*ROW_B + s_0*2, bH + (size_t)r_0 * K + kc + s_0);
        cpa16(sb + OFF_B + r_1*ROW_B + s_1*2, bH + (size_t)r_1 * K + kc + s_1);
        cp_commit();
    };

    #pragma unroll
    for (int s = 0; s < STAGES - 1; s++) issue(s);

    const int arow = wm * 32 + (lane & 15);
    const int acol = (lane >> 4) * 16;
    const int brow = wn * 64 + ((lane >> 4) << 3) + (lane & 7);
    const int bcol = ((lane >> 3) & 1) * 16;

    for (int c = 0; c < NC; c++) {
        if (c + STAGES - 2 < NC) cp_wait<STAGES - 2>();
        else                     cp_wait<0>();
        __syncthreads();
        if (c + STAGES - 1 < NC) issue(c + STAGES - 1);

        const uint32_t sb = sbase + (uint32_t)(c % STAGES) * STAGE_B;

        #pragma unroll
        for (int ks = 0; ks < 2; ks++) {
            const uint32_t kb = ks * 32;
            uint32_t Ah[2][4], Bh[4][4];
            #pragma unroll
            for (int mt = 0; mt < 2; mt++)
                ldsm4(Ah[mt], sb + (arow + mt * 16) * ROW_B + kb + acol);
            #pragma unroll
            for (int bt = 0; bt < 4; bt++)
                ldsm4(Bh[bt], sb + OFF_B + (brow + bt * 16) * ROW_B + kb + bcol);
            #pragma unroll
            for (int mt = 0; mt < 2; mt++)
                #pragma unroll
                for (int bt = 0; bt < 4; bt++) {
                    mma_f16(acc[mt][2*bt],   Ah[mt], Bh[bt][0], Bh[bt][1]);
                    mma_f16(acc[mt][2*bt+1], Ah[mt], Bh[bt][2], Bh[bt][3]);
                }
        }
    }

    // ---- epilogue ----
    const int tg  = lane >> 2;
    const int tc2 = (lane & 3) * 2;
    const int h   = (n0 + wn * 64) >> 6;

    #pragma unroll
    for (int mt = 0; mt < 2; mt++) {
        const int r0 = m0 + wm * 32 + mt * 16 + tg;
        const int r1 = r0 + 8;
        float gv0 = 1.f, gv1 = 1.f;
        if (G) {
            gv0 = gate[(((size_t)(r0 >> 9)) * NH + h) * LEN + (r0 & 511)];
            gv1 = gate[(((size_t)(r1 >> 9)) * NH + h) * LEN + (r1 & 511)];
        }
        #pragma unroll
        for (int nt = 0; nt < 8; nt++) {
            const int cn = n0 + wn * 64 + nt * 8 + tc2;
            const float bs0 = bias[cn], bs1 = bias[cn + 1];
            const float v00 = (acc[mt][nt][0] + bs0) * gv0;
            const float v01 = (acc[mt][nt][1] + bs1) * gv0;
            const float v10 = (acc[mt][nt][2] + bs0) * gv1;
            const float v11 = (acc[mt][nt][3] + bs1) * gv1;
            if (OM == 0) {
                if (r0 < M) *(float2*)&Cf[(size_t)r0 * N + cn] = make_float2(v00, v01);
                if (r1 < M) *(float2*)&Cf[(size_t)r1 * N + cn] = make_float2(v10, v11);
            } else {
                __half2 H0, H1;
                H0.x = __float2half_rn(v00); H0.y = __float2half_rn(v01);
                H1.x = __float2half_rn(v10); H1.y = __float2half_rn(v11);
                if (r0 < M) *(__half2*)(Chi + (size_t)r0 * N + cn) = H0;
                if (r1 < M) *(__half2*)(Chi + (size_t)r1 * N + cn) = H1;
            }
        }
    }
}

// ============================================================================
// qe_score -> back gate (sigmoid) + fcw output
// ============================================================================
__global__ __launch_bounds__(256)
void qe_kernel(const float* __restrict__ qe,
               const float* __restrict__ cw,
               const float* __restrict__ lambdas,
               const float* __restrict__ scores,
               float* __restrict__ back,
               float* __restrict__ fcw)
{
    __shared__ float sc_s[NH][513];
    __shared__ float qe_t[64][33];

    const int b  = blockIdx.x;
    const int i0 = blockIdx.y * 64;
    const int t  = threadIdx.x;

    for (int i = t; i < NH * LEN; i += 256)
        sc_s[i >> 9][i & 511] = scores[(size_t)b * NH * LEN + i];

    const int il = t >> 2;
    const int hg = t & 3;
    float acc[4] = {0.f, 0.f, 0.f, 0.f};

    for (int jc = 0; jc < 16; jc++) {
        __syncthreads();
        #pragma unroll
        for (int p = 0; p < 8; p++) {
            const int f = t + p * 256;
            const int r = f >> 5, c = f & 31;
            qe_t[r][c] = qe[((size_t)b * LEN + i0 + r) * LEN + jc * 32 + c];
        }
        __syncthreads();
        #pragma unroll
        for (int jj = 0; jj < 32; jj++) {
            const float qv = qe_t[il][jj];
            const int j = jc * 32 + jj;
            acc[0] = fmaf(qv, sc_s[hg     ][j], acc[0]);
            acc[1] = fmaf(qv, sc_s[hg + 4 ][j], acc[1]);
            acc[2] = fmaf(qv, sc_s[hg + 8 ][j], acc[2]);
            acc[3] = fmaf(qv, sc_s[hg + 12][j], acc[3]);
        }
    }

    const float c_w = cw[(size_t)b * LEN + i0 + il];
    #pragma unroll
    for (int c = 0; c < 4; c++) {
        const int h = hg + 4 * c;
        const float lam = lambdas[h];
        const float x = acc[c];
        const float z = lam * c_w + (1.f - lam) * x;
        const float bk = 1.f / (1.f + expf(-z));
        back[((size_t)b * NH + h) * LEN + i0 + il] = bk;
        if (h == 0) fcw[(size_t)b * LEN + i0 + il] = x;
    }
}

// ============================================================================
// launch
// ============================================================================
static inline void launch_split1(const float* src, __half* hi, size_t n) {
    size_t n4 = n / 4;
    int blocks = (int)((n4 + 255) / 256);
    split_kernel<<<blocks, 256>>>((const float4*)src, hi, n4);
}

extern "C" void kernel_launch(void* const* d_in, const int* in_sizes, int n_in,
                              void* d_out, int out_size)
{
    const float* q   = (const float*)d_in[0];
    const float* k   = (const float*)d_in[1];
    const float* v   = (const float*)d_in[2];
    const float* cw  = (const float*)d_in[3];
    const float* qe  = (const float*)d_in[4];
    const float* Wq  = (const float*)d_in[5];
    const float* bq  = (const float*)d_in[6];
    const float* Wv  = (const float*)d_in[7];
    const float* bv  = (const float*)d_in[8];
    const float* Wo  = (const float*)d_in[9];
    const float* bo  = (const float*)d_in[10];
    const float* lam = (const float*)d_in[11];

    float* out_main = (float*)d_out;
    float* out_fcw  = (float*)d_out + OUT_MAIN_ELEMS;

    __half *v_hi, *wv_hi, *wo_hi, *c_hi;
    float *qpp, *qp, *wvec, *cbh, *scores, *back;
    cudaGetSymbolAddress((void**)&v_hi,  g_v_hi);
    cudaGetSymbolAddress((void**)&wv_hi, g_wv_hi);
    cudaGetSymbolAddress((void**)&wo_hi, g_wo_hi);
    cudaGetSymbolAddress((void**)&c_hi,  g_c_hi);
    cudaGetSymbolAddress((void**)&qpp,   g_qp_part);
    cudaGetSymbolAddress((void**)&qp,    g_qp);
    cudaGetSymbolAddress((void**)&wvec,  g_w);
    cudaGetSymbolAddress((void**)&cbh,   g_cbh);
    cudaGetSymbolAddress((void**)&scores, g_scores);
    cudaGetSymbolAddress((void**)&back,   g_back);

    const int smem1 = 3 * 2 * COMP_B;   // 61440
    cudaFuncSetAttribute(gemm_mma<3, 1, true>,  cudaFuncAttributeMaxDynamicSharedMemorySize, smem1);
    cudaFuncSetAttribute(gemm_mma<3, 0, false>, cudaFuncAttributeMaxDynamicSharedMemorySize, smem1);

    // conversions
    launch_split1(v,  v_hi,  (size_t)M_KV * 3072);
    launch_split1(Wv, wv_hi, (size_t)1024 * 3072);
    launch_split1(Wo, wo_hi, (size_t)1024 * 1024);

    // 1. query-side folding (exact fp32): qp -> w,cbh -> scores
    qp_part_kernel<<<dim3(8, 32), 256>>>(q, Wq, qpp);
    qp_reduce_kernel<<<64, 256>>>(qpp, bq, qp);
    wfold_kernel<<<dim3(16, 8), 256>>>(qp, Wq, bq, wvec, cbh);
    scores_kernel<<<dim3(BSZ, 4), 256>>>(k, wvec, cbh, scores);

    // 2. qe_score -> gate + fcw
    qe_kernel<<<dim3(BSZ, 8), 256>>>(qe, cw, lam, scores, back, out_fcw);

    // 3. v @ Wv^T + bv, gated -> concat (fp16 out), single-pass fp16
    gemm_mma<3, 1, true><<<dim3(8, 256), 256, smem1>>>(
        v_hi, wv_hi, bv, back, nullptr, c_hi, M_KV, DIM, 3 * DIM);

    // 4. concat @ Wo^T + bo -> main output (fp32), single-pass fp16
    gemm_mma<3, 0, false><<<dim3(8, 256), 256, smem1>>>(
        c_hi, wo_hi, bo, nullptr, out_main, nullptr, M_KV, DIM, DIM);
}